// round 7
// baseline (speedup 1.0000x reference)
#include <cuda_runtime.h>
#include <cuda_fp16.h>
#include <math.h>

#define NN 50000
#define EE 1600000
#define HID 64
#define NC 32
#define NFEAT 128
#define NG 8           // k-groups (64/8)
#define GK 8           // k-cols per group
#define GWH 256        // values per X row = GK*NC
#define CSTF 1e-5f
#define FULL 0xffffffffu
#define NBLK ((NN + 255) / 256)

// ---------------- scratch (device globals; no allocation allowed) ----------
__device__ int    g_deg[NN];
__device__ float  g_dinv[NN];
__device__ int    g_cptr[NN + 1];
__device__ int    g_cnt[NN];
__device__ float2 g_swp[EE];      // packed (src-as-float-bits, wgt)
__device__ int    g_bsum[NBLK];
__device__ int    g_boff[NBLK];
__device__ float  g_x[NN * HID];
__device__ float  g_Q[NN * HID];
__device__ float  g_Kf[NN * HID];
__device__ float  g_V[NN * NC];
__device__ __half g_Kh[NN * HID];
__device__ __half g_Vh[NN * NC];
__device__ __half g_Kha[NN * HID];
__device__ __half g_Khb[NN * HID];
__device__ float  g_coef[4 * NN];
__device__ float  g_tM[HID * NC];
__device__ float  g_tK[HID];
// int8 X buffers: row = 32 uint2 (256 bytes) per node; per-row scale
__device__ uint2  g_X8a[NN * 32];
__device__ uint2  g_X8b[NN * 32];
__device__ float  g_sA[NN];
__device__ float  g_sB[NN];

// ---------------- setup kernels --------------------------------------------
__global__ void k_zero() {
    int i = blockIdx.x * blockDim.x + threadIdx.x;
    if (i < NN) { g_deg[i] = 0; g_cnt[i] = 0; }
    if (i < HID * NC) g_tM[i] = 0.f;
    if (i < HID) g_tK[i] = 0.f;
}

__global__ void k_hist(const int* __restrict__ col) {
    int e = blockIdx.x * blockDim.x + threadIdx.x;
    if (e < EE) atomicAdd(&g_deg[col[e]], 1);
}

__global__ void k_dinv() {
    int i = blockIdx.x * blockDim.x + threadIdx.x;
    if (i < NN) {
        int d = g_deg[i];
        g_dinv[i] = (d > 0) ? 1.0f / (float)d : 0.0f;
    }
}

__global__ void k_blksum() {
    __shared__ int sm[256];
    int b = blockIdx.x, t = threadIdx.x;
    int i = b * 256 + t;
    sm[t] = (i < NN) ? g_deg[i] : 0;
    __syncthreads();
    for (int o = 128; o > 0; o >>= 1) {
        if (t < o) sm[t] += sm[t + o];
        __syncthreads();
    }
    if (t == 0) g_bsum[b] = sm[0];
}

__global__ void k_scanblk() {
    __shared__ int sm[256];
    int t = threadIdx.x;
    int v = (t < NBLK) ? g_bsum[t] : 0;
    sm[t] = v;
    __syncthreads();
    for (int o = 1; o < 256; o <<= 1) {
        int u = 0;
        if (t >= o) u = sm[t - o];
        __syncthreads();
        sm[t] += u;
        __syncthreads();
    }
    if (t < NBLK) g_boff[t] = sm[t] - v;
}

__global__ void k_cptr() {
    __shared__ int sm[256];
    int b = blockIdx.x, t = threadIdx.x;
    int i = b * 256 + t;
    int v = (i < NN) ? g_deg[i] : 0;
    sm[t] = v;
    __syncthreads();
    for (int o = 1; o < 256; o <<= 1) {
        int u = 0;
        if (t >= o) u = sm[t - o];
        __syncthreads();
        sm[t] += u;
        __syncthreads();
    }
    int incl = sm[t];
    if (i < NN) g_cptr[i] = g_boff[b] + incl - v;
    if (i == NN - 1) g_cptr[NN] = g_boff[b] + incl;
}

__global__ void k_scatter(const int* __restrict__ row, const int* __restrict__ col) {
    int e = blockIdx.x * blockDim.x + threadIdx.x;
    if (e < EE) {
        int c = col[e];
        int r = row[e];
        int pos = g_cptr[c] + atomicAdd(&g_cnt[c], 1);
        g_swp[pos] = make_float2(__int_as_float(r), g_dinv[r]);
    }
}

// ---------------- input GEMMs ----------------------------------------------
__global__ void k_gemmA(const float* __restrict__ nf, const float* __restrict__ W,
                        const float* __restrict__ b) {
    __shared__ __align__(16) float Ws[NFEAT * HID];
    __shared__ __align__(16) float xs[16 * NFEAT];
    __shared__ __align__(16) float bs[HID];
    int tid = threadIdx.y * 16 + threadIdx.x;
    for (int i = tid; i < NFEAT * HID; i += 256) Ws[i] = W[i];
    if (tid < HID) bs[tid] = b[tid];
    int nb = blockIdx.x * 16;
    for (int i = tid; i < 16 * NFEAT; i += 256) {
        int n = i >> 7, f = i & 127;
        xs[i] = nf[(nb + n) * NFEAT + f];
    }
    __syncthreads();
    int node = nb + threadIdx.y;
    int oq = threadIdx.x;
    float4 acc = *(const float4*)&bs[oq * 4];
    const float* xr = &xs[threadIdx.y * NFEAT];
#pragma unroll 8
    for (int f = 0; f < NFEAT; f++) {
        float v = xr[f];
        float4 w = *(const float4*)&Ws[f * HID + oq * 4];
        acc.x += v * w.x; acc.y += v * w.y; acc.z += v * w.z; acc.w += v * w.w;
    }
    acc.x = fmaxf(acc.x, 0.f); acc.y = fmaxf(acc.y, 0.f);
    acc.z = fmaxf(acc.z, 0.f); acc.w = fmaxf(acc.w, 0.f);
    *(float4*)&g_x[node * HID + oq * 4] = acc;
}

__global__ void k_gemmB(const float* __restrict__ WQ, const float* __restrict__ bQ,
                        const float* __restrict__ WK, const float* __restrict__ bK,
                        const float* __restrict__ WV, const float* __restrict__ bV) {
    __shared__ __align__(16) float Wc[HID * 160];
    __shared__ __align__(16) float xs[8 * HID];
    __shared__ __align__(16) float bc[160];
    int tid = threadIdx.y * 40 + threadIdx.x;  // 320 threads
    for (int i = tid; i < HID * 160; i += 320) {
        int f = i / 160, o = i % 160;
        float v;
        if (o < 64) v = WQ[f * 64 + o];
        else if (o < 128) v = WK[f * 64 + (o - 64)];
        else v = WV[f * 32 + (o - 128)];
        Wc[i] = v;
    }
    if (tid < 160)
        bc[tid] = (tid < 64) ? bQ[tid] : ((tid < 128) ? bK[tid - 64] : bV[tid - 128]);
    int nb = blockIdx.x * 8;
    for (int i = tid; i < 8 * HID; i += 320) {
        int n = i >> 6, f = i & 63;
        xs[i] = g_x[(nb + n) * HID + f];
    }
    __syncthreads();
    int node = nb + threadIdx.y;
    int oq = threadIdx.x;
    float4 acc = *(const float4*)&bc[oq * 4];
    const float* xr = &xs[threadIdx.y * HID];
#pragma unroll 8
    for (int f = 0; f < HID; f++) {
        float v = xr[f];
        float4 w = *(const float4*)&Wc[f * 160 + oq * 4];
        acc.x += v * w.x; acc.y += v * w.y; acc.z += v * w.z; acc.w += v * w.w;
    }
    if (oq < 32) {
        float4 r;
        r.x = acc.x > 0.f ? 1.f + acc.x : expf(acc.x);
        r.y = acc.y > 0.f ? 1.f + acc.y : expf(acc.y);
        r.z = acc.z > 0.f ? 1.f + acc.z : expf(acc.z);
        r.w = acc.w > 0.f ? 1.f + acc.w : expf(acc.w);
        if (oq < 16) {
            *(float4*)&g_Q[node * HID + oq * 4] = r;
        } else {
            *(float4*)&g_Kf[node * HID + (oq - 16) * 4] = r;
            __half2* kh = (__half2*)&g_Kh[node * HID + (oq - 16) * 4];
            kh[0] = __floats2half2_rn(r.x, r.y);
            kh[1] = __floats2half2_rn(r.z, r.w);
        }
    } else {
        *(float4*)&g_V[node * NC + (oq - 32) * 4] = acc;
        __half2* vh = (__half2*)&g_Vh[node * NC + (oq - 32) * 4];
        vh[0] = __floats2half2_rn(acc.x, acc.y);
        vh[1] = __floats2half2_rn(acc.z, acc.w);
    }
}

// ---------------- teleport reduction ---------------------------------------
__global__ void k_tele() {
    __shared__ __align__(16) float sK[8 * HID];
    __shared__ __align__(16) float sV[8 * NC];
    int tid = threadIdx.x;  // 256
    float accM[8];
#pragma unroll
    for (int j = 0; j < 8; j++) accM[j] = 0.f;
    float accK = 0.f;
    for (int nb = blockIdx.x * 8; nb < NN; nb += gridDim.x * 8) {
        __syncthreads();
        for (int i = tid; i < 8 * HID; i += 256) {
            int n = i >> 6, f = i & 63;
            int node = nb + n;
            sK[i] = (node < NN) ? g_Kf[node * HID + f] : 0.f;
        }
        for (int i = tid; i < 8 * NC; i += 256) {
            int n = i >> 5, c = i & 31;
            int node = nb + n;
            sV[i] = (node < NN) ? g_V[node * NC + c] : 0.f;
        }
        __syncthreads();
#pragma unroll
        for (int j = 0; j < 8; j++) {
            int cell = j * 256 + tid;
            int ii = cell >> 5, cc = cell & 31;
            float a = 0.f;
#pragma unroll
            for (int n = 0; n < 8; n++) a += sK[n * HID + ii] * sV[n * NC + cc];
            accM[j] += a;
        }
        if (tid < HID) {
            float a = 0.f;
#pragma unroll
            for (int n = 0; n < 8; n++) a += sK[n * HID + tid];
            accK += a;
        }
    }
#pragma unroll
    for (int j = 0; j < 8; j++) atomicAdd(&g_tM[j * 256 + tid], accM[j]);
    if (tid < HID) atomicAdd(&g_tK[tid], accK);
}

// hidden init: hopwise[0]*V + teleport * (Q@tM/n) / (Q.tK/n + CST)
__global__ void k_init(const float* __restrict__ hopwise,
                       const float* __restrict__ teleport,
                       float* __restrict__ out) {
    __shared__ __align__(16) float sM[HID * NC];
    __shared__ float sKn[HID];
    int tid = threadIdx.x;
    const float inv_n = 1.0f / (float)NN;
    for (int i = tid; i < HID * NC; i += 256) sM[i] = g_tM[i] * inv_n;
    if (tid < HID) sKn[tid] = g_tK[tid] * inv_n;
    __syncthreads();
    int w = tid >> 5, lane = tid & 31;
    int j = blockIdx.x * 8 + w;
    if (j >= NN) return;
    float q0 = g_Q[j * HID + lane];
    float q1 = g_Q[j * HID + 32 + lane];
    float th = 0.f;
#pragma unroll
    for (int i = 0; i < 32; i++) th += __shfl_sync(FULL, q0, i) * sM[i * NC + lane];
#pragma unroll
    for (int i = 0; i < 32; i++) th += __shfl_sync(FULL, q1, i) * sM[(i + 32) * NC + lane];
    float p = q0 * sKn[lane] + q1 * sKn[32 + lane];
#pragma unroll
    for (int o = 16; o > 0; o >>= 1) p += __shfl_xor_sync(FULL, p, o);
    float tc = p + CSTF;
    out[j * NC + lane] = hopwise[0] * g_V[j * NC + lane] + teleport[0] * th / tc;
}

// ---------------- Kf propagation (fp16 rows) + coef ------------------------
__global__ void k_propK(int in_sel, int out_sel, const float* __restrict__ hopwise, int hop) {
    const __half* Kin = in_sel == 0 ? g_Kh : (in_sel == 1 ? g_Kha : g_Khb);
    __half* Kout = out_sel == 1 ? g_Kha : g_Khb;
    int w = threadIdx.x >> 5, lane = threadIdx.x & 31;
    int j = blockIdx.x * 8 + w;
    if (j >= NN) return;
    int r0 = g_cptr[j], r1 = g_cptr[j + 1];
    float2 acc = make_float2(0.f, 0.f);
    int off = 2 * lane;
    for (int base = r0; base < r1; base += 32) {
        int idx = base + lane;
        int s = 0; float ww = 0.f;
        if (idx < r1) {
            float2 sw = g_swp[idx];
            s = __float_as_int(sw.x); ww = sw.y;
        }
        int mm = min(32, r1 - base);
        int mmr = (mm + 3) & ~3;
        for (int i = 0; i < mmr; i += 4) {
            int s0 = __shfl_sync(FULL, s, i);
            int s1 = __shfl_sync(FULL, s, i + 1);
            int s2 = __shfl_sync(FULL, s, i + 2);
            int s3 = __shfl_sync(FULL, s, i + 3);
            float w0 = __shfl_sync(FULL, ww, i);
            float w1 = __shfl_sync(FULL, ww, i + 1);
            float w2 = __shfl_sync(FULL, ww, i + 2);
            float w3 = __shfl_sync(FULL, ww, i + 3);
            float2 k0 = __half22float2(*(const __half2*)&Kin[s0 * HID + off]);
            float2 k1 = __half22float2(*(const __half2*)&Kin[s1 * HID + off]);
            float2 k2 = __half22float2(*(const __half2*)&Kin[s2 * HID + off]);
            float2 k3 = __half22float2(*(const __half2*)&Kin[s3 * HID + off]);
            acc.x += w0 * k0.x; acc.y += w0 * k0.y;
            acc.x += w1 * k1.x; acc.y += w1 * k1.y;
            acc.x += w2 * k2.x; acc.y += w2 * k2.y;
            acc.x += w3 * k3.x; acc.y += w3 * k3.y;
        }
    }
    *(__half2*)&Kout[j * HID + off] = __floats2half2_rn(acc.x, acc.y);
    float2 q = *(const float2*)&g_Q[j * HID + off];
    float p = q.x * acc.x + q.y * acc.y;
#pragma unroll
    for (int o = 16; o > 0; o >>= 1) p += __shfl_xor_sync(FULL, p, o);
    if (lane == 0) g_coef[(hop - 1) * NN + j] = hopwise[hop] / (p + CSTF);
}

// ---------------- shared epilogue: Q-contract + out accumulate --------------
__device__ __forceinline__ void epilogue(float f[8], int j, int lane, int qoff,
                                         const float* coefh, float* out) {
    float qv = g_Q[j * HID + qoff + (lane >> 2)];
#pragma unroll
    for (int m = 0; m < 8; m++) f[m] *= qv;
#pragma unroll
    for (int mask = 4; mask <= 16; mask <<= 1) {
#pragma unroll
        for (int m = 0; m < 8; m++) f[m] += __shfl_xor_sync(FULL, f[m], mask);
    }
    if (lane < 4) {
        float cf = coefh[j];
        float4* o = (float4*)&out[j * NC + lane * 8];
        float4 o0 = o[0], o1 = o[1];
        o0.x += cf * f[0]; o0.y += cf * f[1]; o0.z += cf * f[2]; o0.w += cf * f[3];
        o1.x += cf * f[4]; o1.y += cf * f[5]; o1.z += cf * f[6]; o1.w += cf * f[7];
        o[0] = o0; o[1] = o1;
    }
}

// quantize row (32 lanes x 8 vals) to int8 with per-row scale; store
__device__ __forceinline__ void quant_store(const float f[8], int j, int lane,
                                            uint2* __restrict__ Xout,
                                            float* __restrict__ sOut) {
    float m = 0.f;
#pragma unroll
    for (int t = 0; t < 8; t++) m = fmaxf(m, fabsf(f[t]));
#pragma unroll
    for (int o = 16; o > 0; o >>= 1) m = fmaxf(m, __shfl_xor_sync(FULL, m, o));
    float inv = (m > 0.f) ? __fdividef(127.f, m) : 0.f;
    int q[8];
#pragma unroll
    for (int t = 0; t < 8; t++) q[t] = __float2int_rn(f[t] * inv);
    unsigned lo = (q[0] & 255) | ((q[1] & 255) << 8) | ((q[2] & 255) << 16) | (q[3] << 24);
    unsigned hi = (q[4] & 255) | ((q[5] & 255) << 8) | ((q[6] & 255) << 16) | (q[7] << 24);
    Xout[j * 32 + lane] = make_uint2(lo, hi);
    if (lane == 0) sOut[j] = m * (1.f / 127.f);
}

__device__ __forceinline__ void acc8h(float f[8], uint4 xv, float wv) {
    float2 p0 = __half22float2(*(__half2*)&xv.x);
    float2 p1 = __half22float2(*(__half2*)&xv.y);
    float2 p2 = __half22float2(*(__half2*)&xv.z);
    float2 p3 = __half22float2(*(__half2*)&xv.w);
    f[0] += wv * p0.x; f[1] += wv * p0.y;
    f[2] += wv * p1.x; f[3] += wv * p1.y;
    f[4] += wv * p2.x; f[5] += wv * p2.y;
    f[6] += wv * p3.x; f[7] += wv * p3.y;
}

__device__ __forceinline__ void acc8q(float f[8], uint2 xv, float wsc) {
    unsigned a = xv.x, b = xv.y;
    f[0] += wsc * (float)(int)(signed char)(a);
    f[1] += wsc * (float)(int)(signed char)(a >> 8);
    f[2] += wsc * (float)(int)(signed char)(a >> 16);
    f[3] += wsc * (float)((int)a >> 24);
    f[4] += wsc * (float)(int)(signed char)(b);
    f[5] += wsc * (float)(int)(signed char)(b >> 8);
    f[6] += wsc * (float)(int)(signed char)(b >> 16);
    f[7] += wsc * (float)((int)b >> 24);
}

// ---------------- hop 1: rank-1 fused gather (Kf ⊗ V), writes int8 X1 -> b --
__global__ void k_prop1(int qoff, float* __restrict__ out) {
    int w = threadIdx.x >> 5, lane = threadIdx.x & 31;
    int j = blockIdx.x * 8 + w;
    if (j >= NN) return;
    int r0 = g_cptr[j], r1 = g_cptr[j + 1];
    int kk = qoff + (lane >> 2);
    int c0 = (lane & 3) * 8;
    float f[8];
#pragma unroll
    for (int m = 0; m < 8; m++) f[m] = 0.f;
    for (int base = r0; base < r1; base += 32) {
        int idx = base + lane;
        int s = 0; float ww = 0.f;
        if (idx < r1) {
            float2 sw = g_swp[idx];
            s = __float_as_int(sw.x); ww = sw.y;
        }
        int mm = min(32, r1 - base);
        int mmr = (mm + 3) & ~3;
        for (int i = 0; i < mmr; i += 4) {
            int s0 = __shfl_sync(FULL, s, i);
            int s1 = __shfl_sync(FULL, s, i + 1);
            int s2 = __shfl_sync(FULL, s, i + 2);
            int s3 = __shfl_sync(FULL, s, i + 3);
            float w0 = __shfl_sync(FULL, ww, i);
            float w1 = __shfl_sync(FULL, ww, i + 1);
            float w2 = __shfl_sync(FULL, ww, i + 2);
            float w3 = __shfl_sync(FULL, ww, i + 3);
            uint4 v0 = *(const uint4*)&g_Vh[s0 * NC + c0];
            uint4 v1 = *(const uint4*)&g_Vh[s1 * NC + c0];
            uint4 v2 = *(const uint4*)&g_Vh[s2 * NC + c0];
            uint4 v3 = *(const uint4*)&g_Vh[s3 * NC + c0];
            float k0 = w0 * __half2float(g_Kh[s0 * HID + kk]);
            float k1 = w1 * __half2float(g_Kh[s1 * HID + kk]);
            float k2 = w2 * __half2float(g_Kh[s2 * HID + kk]);
            float k3 = w3 * __half2float(g_Kh[s3 * HID + kk]);
            acc8h(f, v0, k0);
            acc8h(f, v1, k1);
            acc8h(f, v2, k2);
            acc8h(f, v3, k3);
        }
    }
    quant_store(f, j, lane, g_X8b, g_sB);
    epilogue(f, j, lane, qoff, g_coef, out);
}

// ---------------- hops 2..4: int8 X gather, MLP=4 --------------------------
__global__ void k_propM(int swap, int writeX, int hop, int qoff, float* __restrict__ out) {
    const uint2* Xin = swap ? g_X8b : g_X8a;
    uint2* Xout = swap ? g_X8a : g_X8b;
    const float* sIn = swap ? g_sB : g_sA;
    float* sOut = swap ? g_sA : g_sB;
    const float* coefh = g_coef + (hop - 1) * NN;
    int w = threadIdx.x >> 5, lane = threadIdx.x & 31;
    int j = blockIdx.x * 8 + w;
    if (j >= NN) return;
    int r0 = g_cptr[j], r1 = g_cptr[j + 1];
    float f[8];
#pragma unroll
    for (int m = 0; m < 8; m++) f[m] = 0.f;
    for (int base = r0; base < r1; base += 32) {
        int idx = base + lane;
        int s = 0; float ww = 0.f;
        if (idx < r1) {
            float2 sw = g_swp[idx];
            s = __float_as_int(sw.x); ww = sw.y;
        }
        int mm = min(32, r1 - base);
        int mmr = (mm + 3) & ~3;
        for (int i = 0; i < mmr; i += 4) {
            int s0 = __shfl_sync(FULL, s, i);
            int s1 = __shfl_sync(FULL, s, i + 1);
            int s2 = __shfl_sync(FULL, s, i + 2);
            int s3 = __shfl_sync(FULL, s, i + 3);
            float w0 = __shfl_sync(FULL, ww, i);
            float w1 = __shfl_sync(FULL, ww, i + 1);
            float w2 = __shfl_sync(FULL, ww, i + 2);
            float w3 = __shfl_sync(FULL, ww, i + 3);
            uint2 x0 = Xin[s0 * 32 + lane];
            uint2 x1 = Xin[s1 * 32 + lane];
            uint2 x2 = Xin[s2 * 32 + lane];
            uint2 x3 = Xin[s3 * 32 + lane];
            float c0 = w0 * sIn[s0];
            float c1 = w1 * sIn[s1];
            float c2 = w2 * sIn[s2];
            float c3 = w3 * sIn[s3];
            acc8q(f, x0, c0);
            acc8q(f, x1, c1);
            acc8q(f, x2, c2);
            acc8q(f, x3, c3);
        }
    }
    if (writeX) quant_store(f, j, lane, Xout, sOut);
    epilogue(f, j, lane, qoff, coefh, out);
}

// ---------------- launch ----------------------------------------------------
extern "C" void kernel_launch(void* const* d_in, const int* in_sizes, int n_in,
                              void* d_out, int out_size) {
    const float* nf       = (const float*)d_in[0];
    const float* W_in     = (const float*)d_in[1];
    const float* b_in     = (const float*)d_in[2];
    const float* WQ       = (const float*)d_in[3];
    const float* bQ       = (const float*)d_in[4];
    const float* WK       = (const float*)d_in[5];
    const float* bK       = (const float*)d_in[6];
    const float* WV       = (const float*)d_in[7];
    const float* bV       = (const float*)d_in[8];
    const float* hopwise  = (const float*)d_in[9];
    const float* teleport = (const float*)d_in[10];
    const int*   ei       = (const int*)d_in[11];
    const int* row = ei;
    const int* col = ei + EE;
    float* out = (float*)d_out;

    k_zero<<<(NN + 255) / 256, 256>>>();
    k_hist<<<EE / 256, 256>>>(col);
    k_dinv<<<(NN + 255) / 256, 256>>>();
    k_blksum<<<NBLK, 256>>>();
    k_scanblk<<<1, 256>>>();
    k_cptr<<<NBLK, 256>>>();
    k_scatter<<<EE / 256, 256>>>(row, col);
    k_gemmA<<<NN / 16, dim3(16, 16)>>>(nf, W_in, b_in);
    k_gemmB<<<NN / 8, dim3(40, 8)>>>(WQ, bQ, WK, bK, WV, bV);
    k_tele<<<200, 256>>>();
    k_init<<<NN / 8, 256>>>(hopwise, teleport, out);
    // Kf hops (fp16 rows): Kh -> Ka -> Kb -> Ka -> Kb; coef per hop
    k_propK<<<NN / 8, 256>>>(0, 1, hopwise, 1);
    k_propK<<<NN / 8, 256>>>(1, 2, hopwise, 2);
    k_propK<<<NN / 8, 256>>>(2, 1, hopwise, 3);
    k_propK<<<NN / 8, 256>>>(1, 2, hopwise, 4);
    // M propagation per 8-wide k-group; hop1 fused rank-1 -> int8 X, hops 2-4 int8
    for (int g = 0; g < NG; g++) {
        k_prop1<<<NN / 8, 256>>>(g * GK, out);          // -> X8b (hop 1)
        k_propM<<<NN / 8, 256>>>(1, 1, 2, g * GK, out); // X8b -> X8a
        k_propM<<<NN / 8, 256>>>(0, 1, 3, g * GK, out); // X8a -> X8b
        k_propM<<<NN / 8, 256>>>(1, 0, 4, g * GK, out); // X8b (no write)
    }
}

// round 9
// speedup vs baseline: 1.0485x; 1.0485x over previous
#include <cuda_runtime.h>
#include <cuda_fp16.h>
#include <math.h>

#define NN 50000
#define EE 1600000
#define HID 64
#define NC 32
#define NFEAT 128
#define NG 8           // k-groups (64/8)
#define GK 8           // k-cols per group
#define CSTF 1e-5f
#define FULL 0xffffffffu
#define NBLK ((NN + 255) / 256)
#define MAGIC 0x4B000000u      // fp32 2^23 exponent pattern
#define BIASF 8388736.0f       // 2^23 + 128

// ---------------- scratch (device globals; no allocation allowed) ----------
__device__ int    g_deg[NN];
__device__ float  g_dinv[NN];
__device__ int    g_cptr[NN + 1];
__device__ int    g_cnt[NN];
__device__ float2 g_swp[EE];      // packed (src-as-float-bits, wgt)
__device__ int    g_bsum[NBLK];
__device__ int    g_boff[NBLK];
__device__ float  g_x[NN * HID];
__device__ float  g_Q[NN * HID];
__device__ float  g_Kf[NN * HID];
__device__ float  g_V[NN * NC];
__device__ __half g_Kh[NN * HID];
__device__ __half g_Vh[NN * NC];
__device__ __half g_Kha[NN * HID];
__device__ __half g_Khb[NN * HID];
__device__ float  g_coef[4 * NN];
__device__ float  g_tM[HID * NC];
__device__ float  g_tK[HID];
// int8 X buffers: row = 32 uint2 (256 bytes) per node, biased bytes; per-row scale
__device__ uint2  g_X8a[NN * 32];
__device__ uint2  g_X8b[NN * 32];
__device__ float  g_sA[NN];
__device__ float  g_sB[NN];

// ---------------- setup kernels --------------------------------------------
__global__ void k_zero() {
    int i = blockIdx.x * blockDim.x + threadIdx.x;
    if (i < NN) { g_deg[i] = 0; g_cnt[i] = 0; }
    if (i < HID * NC) g_tM[i] = 0.f;
    if (i < HID) g_tK[i] = 0.f;
}

__global__ void k_hist(const int* __restrict__ col) {
    int e = blockIdx.x * blockDim.x + threadIdx.x;
    if (e < EE) atomicAdd(&g_deg[col[e]], 1);
}

__global__ void k_dinv() {
    int i = blockIdx.x * blockDim.x + threadIdx.x;
    if (i < NN) {
        int d = g_deg[i];
        g_dinv[i] = (d > 0) ? 1.0f / (float)d : 0.0f;
    }
}

__global__ void k_blksum() {
    __shared__ int sm[256];
    int b = blockIdx.x, t = threadIdx.x;
    int i = b * 256 + t;
    sm[t] = (i < NN) ? g_deg[i] : 0;
    __syncthreads();
    for (int o = 128; o > 0; o >>= 1) {
        if (t < o) sm[t] += sm[t + o];
        __syncthreads();
    }
    if (t == 0) g_bsum[b] = sm[0];
}

__global__ void k_scanblk() {
    __shared__ int sm[256];
    int t = threadIdx.x;
    int v = (t < NBLK) ? g_bsum[t] : 0;
    sm[t] = v;
    __syncthreads();
    for (int o = 1; o < 256; o <<= 1) {
        int u = 0;
        if (t >= o) u = sm[t - o];
        __syncthreads();
        sm[t] += u;
        __syncthreads();
    }
    if (t < NBLK) g_boff[t] = sm[t] - v;
}

__global__ void k_cptr() {
    __shared__ int sm[256];
    int b = blockIdx.x, t = threadIdx.x;
    int i = b * 256 + t;
    int v = (i < NN) ? g_deg[i] : 0;
    sm[t] = v;
    __syncthreads();
    for (int o = 1; o < 256; o <<= 1) {
        int u = 0;
        if (t >= o) u = sm[t - o];
        __syncthreads();
        sm[t] += u;
        __syncthreads();
    }
    int incl = sm[t];
    if (i < NN) g_cptr[i] = g_boff[b] + incl - v;
    if (i == NN - 1) g_cptr[NN] = g_boff[b] + incl;
}

__global__ void k_scatter(const int* __restrict__ row, const int* __restrict__ col) {
    int e = blockIdx.x * blockDim.x + threadIdx.x;
    if (e < EE) {
        int c = col[e];
        int r = row[e];
        int pos = g_cptr[c] + atomicAdd(&g_cnt[c], 1);
        g_swp[pos] = make_float2(__int_as_float(r), g_dinv[r]);
    }
}

// ---------------- input GEMMs ----------------------------------------------
__global__ void k_gemmA(const float* __restrict__ nf, const float* __restrict__ W,
                        const float* __restrict__ b) {
    __shared__ __align__(16) float Ws[NFEAT * HID];
    __shared__ __align__(16) float xs[16 * NFEAT];
    __shared__ __align__(16) float bs[HID];
    int tid = threadIdx.y * 16 + threadIdx.x;
    for (int i = tid; i < NFEAT * HID; i += 256) Ws[i] = W[i];
    if (tid < HID) bs[tid] = b[tid];
    int nb = blockIdx.x * 16;
    for (int i = tid; i < 16 * NFEAT; i += 256) {
        int n = i >> 7, f = i & 127;
        xs[i] = nf[(nb + n) * NFEAT + f];
    }
    __syncthreads();
    int node = nb + threadIdx.y;
    int oq = threadIdx.x;
    float4 acc = *(const float4*)&bs[oq * 4];
    const float* xr = &xs[threadIdx.y * NFEAT];
#pragma unroll 8
    for (int f = 0; f < NFEAT; f++) {
        float v = xr[f];
        float4 w = *(const float4*)&Ws[f * HID + oq * 4];
        acc.x += v * w.x; acc.y += v * w.y; acc.z += v * w.z; acc.w += v * w.w;
    }
    acc.x = fmaxf(acc.x, 0.f); acc.y = fmaxf(acc.y, 0.f);
    acc.z = fmaxf(acc.z, 0.f); acc.w = fmaxf(acc.w, 0.f);
    *(float4*)&g_x[node * HID + oq * 4] = acc;
}

__global__ void k_gemmB(const float* __restrict__ WQ, const float* __restrict__ bQ,
                        const float* __restrict__ WK, const float* __restrict__ bK,
                        const float* __restrict__ WV, const float* __restrict__ bV) {
    __shared__ __align__(16) float Wc[HID * 160];
    __shared__ __align__(16) float xs[8 * HID];
    __shared__ __align__(16) float bc[160];
    int tid = threadIdx.y * 40 + threadIdx.x;  // 320 threads
    for (int i = tid; i < HID * 160; i += 320) {
        int f = i / 160, o = i % 160;
        float v;
        if (o < 64) v = WQ[f * 64 + o];
        else if (o < 128) v = WK[f * 64 + (o - 64)];
        else v = WV[f * 32 + (o - 128)];
        Wc[i] = v;
    }
    if (tid < 160)
        bc[tid] = (tid < 64) ? bQ[tid] : ((tid < 128) ? bK[tid - 64] : bV[tid - 128]);
    int nb = blockIdx.x * 8;
    for (int i = tid; i < 8 * HID; i += 320) {
        int n = i >> 6, f = i & 63;
        xs[i] = g_x[(nb + n) * HID + f];
    }
    __syncthreads();
    int node = nb + threadIdx.y;
    int oq = threadIdx.x;
    float4 acc = *(const float4*)&bc[oq * 4];
    const float* xr = &xs[threadIdx.y * HID];
#pragma unroll 8
    for (int f = 0; f < HID; f++) {
        float v = xr[f];
        float4 w = *(const float4*)&Wc[f * 160 + oq * 4];
        acc.x += v * w.x; acc.y += v * w.y; acc.z += v * w.z; acc.w += v * w.w;
    }
    if (oq < 32) {
        float4 r;
        r.x = acc.x > 0.f ? 1.f + acc.x : expf(acc.x);
        r.y = acc.y > 0.f ? 1.f + acc.y : expf(acc.y);
        r.z = acc.z > 0.f ? 1.f + acc.z : expf(acc.z);
        r.w = acc.w > 0.f ? 1.f + acc.w : expf(acc.w);
        if (oq < 16) {
            *(float4*)&g_Q[node * HID + oq * 4] = r;
        } else {
            *(float4*)&g_Kf[node * HID + (oq - 16) * 4] = r;
            __half2* kh = (__half2*)&g_Kh[node * HID + (oq - 16) * 4];
            kh[0] = __floats2half2_rn(r.x, r.y);
            kh[1] = __floats2half2_rn(r.z, r.w);
        }
    } else {
        *(float4*)&g_V[node * NC + (oq - 32) * 4] = acc;
        __half2* vh = (__half2*)&g_Vh[node * NC + (oq - 32) * 4];
        vh[0] = __floats2half2_rn(acc.x, acc.y);
        vh[1] = __floats2half2_rn(acc.z, acc.w);
    }
}

// ---------------- teleport reduction ---------------------------------------
__global__ void k_tele() {
    __shared__ __align__(16) float sK[8 * HID];
    __shared__ __align__(16) float sV[8 * NC];
    int tid = threadIdx.x;  // 256
    float accM[8];
#pragma unroll
    for (int j = 0; j < 8; j++) accM[j] = 0.f;
    float accK = 0.f;
    for (int nb = blockIdx.x * 8; nb < NN; nb += gridDim.x * 8) {
        __syncthreads();
        for (int i = tid; i < 8 * HID; i += 256) {
            int n = i >> 6, f = i & 63;
            int node = nb + n;
            sK[i] = (node < NN) ? g_Kf[node * HID + f] : 0.f;
        }
        for (int i = tid; i < 8 * NC; i += 256) {
            int n = i >> 5, c = i & 31;
            int node = nb + n;
            sV[i] = (node < NN) ? g_V[node * NC + c] : 0.f;
        }
        __syncthreads();
#pragma unroll
        for (int j = 0; j < 8; j++) {
            int cell = j * 256 + tid;
            int ii = cell >> 5, cc = cell & 31;
            float a = 0.f;
#pragma unroll
            for (int n = 0; n < 8; n++) a += sK[n * HID + ii] * sV[n * NC + cc];
            accM[j] += a;
        }
        if (tid < HID) {
            float a = 0.f;
#pragma unroll
            for (int n = 0; n < 8; n++) a += sK[n * HID + tid];
            accK += a;
        }
    }
#pragma unroll
    for (int j = 0; j < 8; j++) atomicAdd(&g_tM[j * 256 + tid], accM[j]);
    if (tid < HID) atomicAdd(&g_tK[tid], accK);
}

// hidden init: hopwise[0]*V + teleport * (Q@tM/n) / (Q.tK/n + CST)
__global__ void k_init(const float* __restrict__ hopwise,
                       const float* __restrict__ teleport,
                       float* __restrict__ out) {
    __shared__ __align__(16) float sM[HID * NC];
    __shared__ float sKn[HID];
    int tid = threadIdx.x;
    const float inv_n = 1.0f / (float)NN;
    for (int i = tid; i < HID * NC; i += 256) sM[i] = g_tM[i] * inv_n;
    if (tid < HID) sKn[tid] = g_tK[tid] * inv_n;
    __syncthreads();
    int w = tid >> 5, lane = tid & 31;
    int j = blockIdx.x * 8 + w;
    if (j >= NN) return;
    float q0 = g_Q[j * HID + lane];
    float q1 = g_Q[j * HID + 32 + lane];
    float th = 0.f;
#pragma unroll
    for (int i = 0; i < 32; i++) th += __shfl_sync(FULL, q0, i) * sM[i * NC + lane];
#pragma unroll
    for (int i = 0; i < 32; i++) th += __shfl_sync(FULL, q1, i) * sM[(i + 32) * NC + lane];
    float p = q0 * sKn[lane] + q1 * sKn[32 + lane];
#pragma unroll
    for (int o = 16; o > 0; o >>= 1) p += __shfl_xor_sync(FULL, p, o);
    float tc = p + CSTF;
    out[j * NC + lane] = hopwise[0] * g_V[j * NC + lane] + teleport[0] * th / tc;
}

// ---------------- Kf propagation (fp16 rows) + coef ------------------------
__global__ void k_propK(int in_sel, int out_sel, const float* __restrict__ hopwise, int hop) {
    const __half* Kin = in_sel == 0 ? g_Kh : (in_sel == 1 ? g_Kha : g_Khb);
    __half* Kout = out_sel == 1 ? g_Kha : g_Khb;
    int w = threadIdx.x >> 5, lane = threadIdx.x & 31;
    int j = blockIdx.x * 8 + w;
    if (j >= NN) return;
    int r0 = g_cptr[j], r1 = g_cptr[j + 1];
    float2 acc = make_float2(0.f, 0.f);
    int off = 2 * lane;
    for (int base = r0; base < r1; base += 32) {
        int idx = base + lane;
        int s = 0; float ww = 0.f;
        if (idx < r1) {
            float2 sw = g_swp[idx];
            s = __float_as_int(sw.x); ww = sw.y;
        }
        int mm = min(32, r1 - base);
        int mmr = (mm + 3) & ~3;
        for (int i = 0; i < mmr; i += 4) {
            int s0 = __shfl_sync(FULL, s, i);
            int s1 = __shfl_sync(FULL, s, i + 1);
            int s2 = __shfl_sync(FULL, s, i + 2);
            int s3 = __shfl_sync(FULL, s, i + 3);
            float w0 = __shfl_sync(FULL, ww, i);
            float w1 = __shfl_sync(FULL, ww, i + 1);
            float w2 = __shfl_sync(FULL, ww, i + 2);
            float w3 = __shfl_sync(FULL, ww, i + 3);
            float2 k0 = __half22float2(*(const __half2*)&Kin[s0 * HID + off]);
            float2 k1 = __half22float2(*(const __half2*)&Kin[s1 * HID + off]);
            float2 k2 = __half22float2(*(const __half2*)&Kin[s2 * HID + off]);
            float2 k3 = __half22float2(*(const __half2*)&Kin[s3 * HID + off]);
            acc.x += w0 * k0.x; acc.y += w0 * k0.y;
            acc.x += w1 * k1.x; acc.y += w1 * k1.y;
            acc.x += w2 * k2.x; acc.y += w2 * k2.y;
            acc.x += w3 * k3.x; acc.y += w3 * k3.y;
        }
    }
    *(__half2*)&Kout[j * HID + off] = __floats2half2_rn(acc.x, acc.y);
    float2 q = *(const float2*)&g_Q[j * HID + off];
    float p = q.x * acc.x + q.y * acc.y;
#pragma unroll
    for (int o = 16; o > 0; o >>= 1) p += __shfl_xor_sync(FULL, p, o);
    if (lane == 0) g_coef[(hop - 1) * NN + j] = hopwise[hop] / (p + CSTF);
}

// ---------------- shared epilogue: Q-contract + out accumulate --------------
__device__ __forceinline__ void epilogue(float f[8], int j, int lane, int qoff,
                                         const float* coefh, float* out) {
    float qv = g_Q[j * HID + qoff + (lane >> 2)];
#pragma unroll
    for (int m = 0; m < 8; m++) f[m] *= qv;
#pragma unroll
    for (int mask = 4; mask <= 16; mask <<= 1) {
#pragma unroll
        for (int m = 0; m < 8; m++) f[m] += __shfl_xor_sync(FULL, f[m], mask);
    }
    if (lane < 4) {
        float cf = coefh[j];
        float4* o = (float4*)&out[j * NC + lane * 8];
        float4 o0 = o[0], o1 = o[1];
        o0.x += cf * f[0]; o0.y += cf * f[1]; o0.z += cf * f[2]; o0.w += cf * f[3];
        o1.x += cf * f[4]; o1.y += cf * f[5]; o1.z += cf * f[6]; o1.w += cf * f[7];
        o[0] = o0; o[1] = o1;
    }
}

// quantize row (32 lanes x 8 vals) to biased int8 with per-row scale; store
__device__ __forceinline__ void quant_store(const float f[8], int j, int lane,
                                            uint2* __restrict__ Xout,
                                            float* __restrict__ sOut) {
    float m = 0.f;
#pragma unroll
    for (int t = 0; t < 8; t++) m = fmaxf(m, fabsf(f[t]));
#pragma unroll
    for (int o = 16; o > 0; o >>= 1) m = fmaxf(m, __shfl_xor_sync(FULL, m, o));
    float inv = (m > 0.f) ? __fdividef(127.f, m) : 0.f;
    int q[8];
#pragma unroll
    for (int t = 0; t < 8; t++) q[t] = __float2int_rn(f[t] * inv) + 128;  // [1,255]
    unsigned lo = (unsigned)q[0] | ((unsigned)q[1] << 8) | ((unsigned)q[2] << 16) | ((unsigned)q[3] << 24);
    unsigned hi = (unsigned)q[4] | ((unsigned)q[5] << 8) | ((unsigned)q[6] << 16) | ((unsigned)q[7] << 24);
    Xout[j * 32 + lane] = make_uint2(lo, hi);
    if (lane == 0) sOut[j] = m * (1.f / 127.f);
}

__device__ __forceinline__ void acc8h(float f[8], uint4 xv, float wv) {
    float2 p0 = __half22float2(*(__half2*)&xv.x);
    float2 p1 = __half22float2(*(__half2*)&xv.y);
    float2 p2 = __half22float2(*(__half2*)&xv.z);
    float2 p3 = __half22float2(*(__half2*)&xv.w);
    f[0] += wv * p0.x; f[1] += wv * p0.y;
    f[2] += wv * p1.x; f[3] += wv * p1.y;
    f[4] += wv * p2.x; f[5] += wv * p2.y;
    f[6] += wv * p3.x; f[7] += wv * p3.y;
}

// biased-byte magic dequant with PER-VALUE exact bias removal:
// (2^23|b) - (2^23+128) == b-128 exactly in fp32  -> 1 PRMT + 1 FADD + 1 FFMA
__device__ __forceinline__ void acc8q(float f[8], uint2 xv, float wsc) {
    unsigned a = xv.x, b = xv.y;
    f[0] += wsc * (__uint_as_float(__byte_perm(a, MAGIC, 0x7440u)) - BIASF);
    f[1] += wsc * (__uint_as_float(__byte_perm(a, MAGIC, 0x7441u)) - BIASF);
    f[2] += wsc * (__uint_as_float(__byte_perm(a, MAGIC, 0x7442u)) - BIASF);
    f[3] += wsc * (__uint_as_float(__byte_perm(a, MAGIC, 0x7443u)) - BIASF);
    f[4] += wsc * (__uint_as_float(__byte_perm(b, MAGIC, 0x7440u)) - BIASF);
    f[5] += wsc * (__uint_as_float(__byte_perm(b, MAGIC, 0x7441u)) - BIASF);
    f[6] += wsc * (__uint_as_float(__byte_perm(b, MAGIC, 0x7442u)) - BIASF);
    f[7] += wsc * (__uint_as_float(__byte_perm(b, MAGIC, 0x7443u)) - BIASF);
}

// ---------------- hop 1: rank-1 fused gather (Kf ⊗ V), writes int8 X1 -> b --
__global__ void k_prop1(int qoff, float* __restrict__ out) {
    int w = threadIdx.x >> 5, lane = threadIdx.x & 31;
    int j = blockIdx.x * 8 + w;
    if (j >= NN) return;
    int r0 = g_cptr[j], r1 = g_cptr[j + 1];
    int kk = qoff + (lane >> 2);
    int c0 = (lane & 3) * 8;
    float f[8];
#pragma unroll
    for (int m = 0; m < 8; m++) f[m] = 0.f;
    for (int base = r0; base < r1; base += 32) {
        int idx = base + lane;
        int s = 0; float ww = 0.f;
        if (idx < r1) {
            float2 sw = g_swp[idx];
            s = __float_as_int(sw.x); ww = sw.y;
        }
        int mm = min(32, r1 - base);
        int mmr = (mm + 3) & ~3;
        for (int i = 0; i < mmr; i += 4) {
            int s0 = __shfl_sync(FULL, s, i);
            int s1 = __shfl_sync(FULL, s, i + 1);
            int s2 = __shfl_sync(FULL, s, i + 2);
            int s3 = __shfl_sync(FULL, s, i + 3);
            float w0 = __shfl_sync(FULL, ww, i);
            float w1 = __shfl_sync(FULL, ww, i + 1);
            float w2 = __shfl_sync(FULL, ww, i + 2);
            float w3 = __shfl_sync(FULL, ww, i + 3);
            uint4 v0 = *(const uint4*)&g_Vh[s0 * NC + c0];
            uint4 v1 = *(const uint4*)&g_Vh[s1 * NC + c0];
            uint4 v2 = *(const uint4*)&g_Vh[s2 * NC + c0];
            uint4 v3 = *(const uint4*)&g_Vh[s3 * NC + c0];
            float k0 = w0 * __half2float(g_Kh[s0 * HID + kk]);
            float k1 = w1 * __half2float(g_Kh[s1 * HID + kk]);
            float k2 = w2 * __half2float(g_Kh[s2 * HID + kk]);
            float k3 = w3 * __half2float(g_Kh[s3 * HID + kk]);
            acc8h(f, v0, k0);
            acc8h(f, v1, k1);
            acc8h(f, v2, k2);
            acc8h(f, v3, k3);
        }
    }
    quant_store(f, j, lane, g_X8b, g_sB);
    epilogue(f, j, lane, qoff, g_coef, out);
}

// ---------------- hops 2..4: biased int8 X gather, exact PRMT dequant -------
__global__ void k_propM(int swap, int writeX, int hop, int qoff, float* __restrict__ out) {
    const uint2* Xin = swap ? g_X8b : g_X8a;
    uint2* Xout = swap ? g_X8a : g_X8b;
    const float* sIn = swap ? g_sB : g_sA;
    float* sOut = swap ? g_sA : g_sB;
    const float* coefh = g_coef + (hop - 1) * NN;
    int w = threadIdx.x >> 5, lane = threadIdx.x & 31;
    int j = blockIdx.x * 8 + w;
    if (j >= NN) return;
    int r0 = g_cptr[j], r1 = g_cptr[j + 1];
    float f[8];
#pragma unroll
    for (int m = 0; m < 8; m++) f[m] = 0.f;
    for (int base = r0; base < r1; base += 32) {
        int idx = base + lane;
        int s = 0; float ww = 0.f;
        if (idx < r1) {
            float2 sw = g_swp[idx];
            s = __float_as_int(sw.x); ww = sw.y;
        }
        int mm = min(32, r1 - base);
        int mmr = (mm + 3) & ~3;
        for (int i = 0; i < mmr; i += 4) {
            int s0 = __shfl_sync(FULL, s, i);
            int s1 = __shfl_sync(FULL, s, i + 1);
            int s2 = __shfl_sync(FULL, s, i + 2);
            int s3 = __shfl_sync(FULL, s, i + 3);
            float w0 = __shfl_sync(FULL, ww, i);
            float w1 = __shfl_sync(FULL, ww, i + 1);
            float w2 = __shfl_sync(FULL, ww, i + 2);
            float w3 = __shfl_sync(FULL, ww, i + 3);
            uint2 x0 = Xin[s0 * 32 + lane];
            uint2 x1 = Xin[s1 * 32 + lane];
            uint2 x2 = Xin[s2 * 32 + lane];
            uint2 x3 = Xin[s3 * 32 + lane];
            float c0 = w0 * sIn[s0];
            float c1 = w1 * sIn[s1];
            float c2 = w2 * sIn[s2];
            float c3 = w3 * sIn[s3];
            acc8q(f, x0, c0);
            acc8q(f, x1, c1);
            acc8q(f, x2, c2);
            acc8q(f, x3, c3);
        }
    }
    if (writeX) quant_store(f, j, lane, Xout, sOut);
    epilogue(f, j, lane, qoff, coefh, out);
}

// ---------------- launch ----------------------------------------------------
extern "C" void kernel_launch(void* const* d_in, const int* in_sizes, int n_in,
                              void* d_out, int out_size) {
    const float* nf       = (const float*)d_in[0];
    const float* W_in     = (const float*)d_in[1];
    const float* b_in     = (const float*)d_in[2];
    const float* WQ       = (const float*)d_in[3];
    const float* bQ       = (const float*)d_in[4];
    const float* WK       = (const float*)d_in[5];
    const float* bK       = (const float*)d_in[6];
    const float* WV       = (const float*)d_in[7];
    const float* bV       = (const float*)d_in[8];
    const float* hopwise  = (const float*)d_in[9];
    const float* teleport = (const float*)d_in[10];
    const int*   ei       = (const int*)d_in[11];
    const int* row = ei;
    const int* col = ei + EE;
    float* out = (float*)d_out;

    k_zero<<<(NN + 255) / 256, 256>>>();
    k_hist<<<EE / 256, 256>>>(col);
    k_dinv<<<(NN + 255) / 256, 256>>>();
    k_blksum<<<NBLK, 256>>>();
    k_scanblk<<<1, 256>>>();
    k_cptr<<<NBLK, 256>>>();
    k_scatter<<<EE / 256, 256>>>(row, col);
    k_gemmA<<<NN / 16, dim3(16, 16)>>>(nf, W_in, b_in);
    k_gemmB<<<NN / 8, dim3(40, 8)>>>(WQ, bQ, WK, bK, WV, bV);
    k_tele<<<200, 256>>>();
    k_init<<<NN / 8, 256>>>(hopwise, teleport, out);
    // Kf hops (fp16 rows): Kh -> Ka -> Kb -> Ka -> Kb; coef per hop
    k_propK<<<NN / 8, 256>>>(0, 1, hopwise, 1);
    k_propK<<<NN / 8, 256>>>(1, 2, hopwise, 2);
    k_propK<<<NN / 8, 256>>>(2, 1, hopwise, 3);
    k_propK<<<NN / 8, 256>>>(1, 2, hopwise, 4);
    // M propagation per 8-wide k-group; hop1 fused rank-1 -> int8 X, hops 2-4 int8
    for (int g = 0; g < NG; g++) {
        k_prop1<<<NN / 8, 256>>>(g * GK, out);          // -> X8b (hop 1)
        k_propM<<<NN / 8, 256>>>(1, 1, 2, g * GK, out); // X8b -> X8a
        k_propM<<<NN / 8, 256>>>(0, 1, 3, g * GK, out); // X8a -> X8b
        k_propM<<<NN / 8, 256>>>(1, 0, 4, g * GK, out); // X8b (no write)
    }
}

// round 11
// speedup vs baseline: 1.1441x; 1.0912x over previous
#include <cuda_runtime.h>
#include <cuda_fp16.h>
#include <math.h>

#define NN 50000
#define EE 1600000
#define HID 64
#define NC 32
#define NFEAT 128
#define NG 8           // k-groups (64/8)
#define GK 8           // k-cols per group
#define CSTF 1e-5f
#define FULL 0xffffffffu
#define NBLK ((NN + 255) / 256)

// ---------------- scratch (device globals; no allocation allowed) ----------
__device__ int      g_deg[NN];
__device__ float    g_dinv[NN];
__device__ int      g_cptr[NN + 1];
__device__ int      g_cnt[NN];
__device__ float2   g_swp[EE];     // (src-as-float-bits, w fp32) for propK/prop1
__device__ unsigned g_sw8[EE];     // src | (w8<<16) for propM
__device__ unsigned g_rwU[NN];     // per-target max weight (float bits)
__device__ int      g_bsum[NBLK];
__device__ int      g_boff[NBLK];
__device__ float    g_x[NN * HID];
__device__ float    g_Q[NN * HID];
__device__ float    g_Kf[NN * HID];
__device__ float    g_V[NN * NC];
__device__ __half   g_Kh[NN * HID];
__device__ __half   g_Vh[NN * NC];
__device__ __half   g_Kha[NN * HID];
__device__ __half   g_Khb[NN * HID];
__device__ float    g_coef[4 * NN];
__device__ float    g_tM[HID * NC];
__device__ float    g_tK[HID];
// int8 X buffers: row = 32 uint2 (256 bytes) per node, SIGNED bytes
__device__ uint2    g_X8a[NN * 32];
__device__ uint2    g_X8b[NN * 32];
__device__ float    g_sA[NN];
__device__ float    g_sB[NN];
// per-writer-instance scale slots (24 instances x 256) and global scales
__device__ unsigned g_slotU[24 * 256];
__device__ float    g_GS[24];

// ---------------- setup kernels --------------------------------------------
__global__ void k_zero() {
    int i = blockIdx.x * blockDim.x + threadIdx.x;
    if (i < NN) { g_deg[i] = 0; g_cnt[i] = 0; g_rwU[i] = 0u; }
    if (i < HID * NC) g_tM[i] = 0.f;
    if (i < HID) g_tK[i] = 0.f;
    if (i < 24 * 256) g_slotU[i] = 0u;
}

__global__ void k_hist(const int* __restrict__ col) {
    int e = blockIdx.x * blockDim.x + threadIdx.x;
    if (e < EE) atomicAdd(&g_deg[col[e]], 1);
}

__global__ void k_dinv() {
    int i = blockIdx.x * blockDim.x + threadIdx.x;
    if (i < NN) {
        int d = g_deg[i];
        g_dinv[i] = (d > 0) ? 1.0f / (float)d : 0.0f;
    }
}

// per-target max incoming weight (positive floats compare as uints)
__global__ void k_wmax(const int* __restrict__ row, const int* __restrict__ col) {
    int e = blockIdx.x * blockDim.x + threadIdx.x;
    if (e < EE) atomicMax(&g_rwU[col[e]], __float_as_uint(g_dinv[row[e]]));
}

__global__ void k_blksum() {
    __shared__ int sm[256];
    int b = blockIdx.x, t = threadIdx.x;
    int i = b * 256 + t;
    sm[t] = (i < NN) ? g_deg[i] : 0;
    __syncthreads();
    for (int o = 128; o > 0; o >>= 1) {
        if (t < o) sm[t] += sm[t + o];
        __syncthreads();
    }
    if (t == 0) g_bsum[b] = sm[0];
}

__global__ void k_scanblk() {
    __shared__ int sm[256];
    int t = threadIdx.x;
    int v = (t < NBLK) ? g_bsum[t] : 0;
    sm[t] = v;
    __syncthreads();
    for (int o = 1; o < 256; o <<= 1) {
        int u = 0;
        if (t >= o) u = sm[t - o];
        __syncthreads();
        sm[t] += u;
        __syncthreads();
    }
    if (t < NBLK) g_boff[t] = sm[t] - v;
}

__global__ void k_cptr() {
    __shared__ int sm[256];
    int b = blockIdx.x, t = threadIdx.x;
    int i = b * 256 + t;
    int v = (i < NN) ? g_deg[i] : 0;
    sm[t] = v;
    __syncthreads();
    for (int o = 1; o < 256; o <<= 1) {
        int u = 0;
        if (t >= o) u = sm[t - o];
        __syncthreads();
        sm[t] += u;
        __syncthreads();
    }
    int incl = sm[t];
    if (i < NN) g_cptr[i] = g_boff[b] + incl - v;
    if (i == NN - 1) g_cptr[NN] = g_boff[b] + incl;
}

__global__ void k_scatter(const int* __restrict__ row, const int* __restrict__ col) {
    int e = blockIdx.x * blockDim.x + threadIdx.x;
    if (e < EE) {
        int c = col[e];
        int r = row[e];
        int pos = g_cptr[c] + atomicAdd(&g_cnt[c], 1);
        float w = g_dinv[r];
        g_swp[pos] = make_float2(__int_as_float(r), w);
        float rw = __uint_as_float(g_rwU[c]);
        int w8 = (rw > 0.f) ? (int)rintf(127.f * w / rw) : 0;
        g_sw8[pos] = (unsigned)r | ((unsigned)w8 << 16);
    }
}

// ---------------- input GEMMs ----------------------------------------------
__global__ void k_gemmA(const float* __restrict__ nf, const float* __restrict__ W,
                        const float* __restrict__ b) {
    __shared__ __align__(16) float Ws[NFEAT * HID];
    __shared__ __align__(16) float xs[16 * NFEAT];
    __shared__ __align__(16) float bs[HID];
    int tid = threadIdx.y * 16 + threadIdx.x;
    for (int i = tid; i < NFEAT * HID; i += 256) Ws[i] = W[i];
    if (tid < HID) bs[tid] = b[tid];
    int nb = blockIdx.x * 16;
    for (int i = tid; i < 16 * NFEAT; i += 256) {
        int n = i >> 7, f = i & 127;
        xs[i] = nf[(nb + n) * NFEAT + f];
    }
    __syncthreads();
    int node = nb + threadIdx.y;
    int oq = threadIdx.x;
    float4 acc = *(const float4*)&bs[oq * 4];
    const float* xr = &xs[threadIdx.y * NFEAT];
#pragma unroll 8
    for (int f = 0; f < NFEAT; f++) {
        float v = xr[f];
        float4 w = *(const float4*)&Ws[f * HID + oq * 4];
        acc.x += v * w.x; acc.y += v * w.y; acc.z += v * w.z; acc.w += v * w.w;
    }
    acc.x = fmaxf(acc.x, 0.f); acc.y = fmaxf(acc.y, 0.f);
    acc.z = fmaxf(acc.z, 0.f); acc.w = fmaxf(acc.w, 0.f);
    *(float4*)&g_x[node * HID + oq * 4] = acc;
}

__global__ void k_gemmB(const float* __restrict__ WQ, const float* __restrict__ bQ,
                        const float* __restrict__ WK, const float* __restrict__ bK,
                        const float* __restrict__ WV, const float* __restrict__ bV) {
    __shared__ __align__(16) float Wc[HID * 160];
    __shared__ __align__(16) float xs[8 * HID];
    __shared__ __align__(16) float bc[160];
    int tid = threadIdx.y * 40 + threadIdx.x;  // 320 threads
    for (int i = tid; i < HID * 160; i += 320) {
        int f = i / 160, o = i % 160;
        float v;
        if (o < 64) v = WQ[f * 64 + o];
        else if (o < 128) v = WK[f * 64 + (o - 64)];
        else v = WV[f * 32 + (o - 128)];
        Wc[i] = v;
    }
    if (tid < 160)
        bc[tid] = (tid < 64) ? bQ[tid] : ((tid < 128) ? bK[tid - 64] : bV[tid - 128]);
    int nb = blockIdx.x * 8;
    for (int i = tid; i < 8 * HID; i += 320) {
        int n = i >> 6, f = i & 63;
        xs[i] = g_x[(nb + n) * HID + f];
    }
    __syncthreads();
    int node = nb + threadIdx.y;
    int oq = threadIdx.x;
    float4 acc = *(const float4*)&bc[oq * 4];
    const float* xr = &xs[threadIdx.y * HID];
#pragma unroll 8
    for (int f = 0; f < HID; f++) {
        float v = xr[f];
        float4 w = *(const float4*)&Wc[f * 160 + oq * 4];
        acc.x += v * w.x; acc.y += v * w.y; acc.z += v * w.z; acc.w += v * w.w;
    }
    if (oq < 32) {
        float4 r;
        r.x = acc.x > 0.f ? 1.f + acc.x : expf(acc.x);
        r.y = acc.y > 0.f ? 1.f + acc.y : expf(acc.y);
        r.z = acc.z > 0.f ? 1.f + acc.z : expf(acc.z);
        r.w = acc.w > 0.f ? 1.f + acc.w : expf(acc.w);
        if (oq < 16) {
            *(float4*)&g_Q[node * HID + oq * 4] = r;
        } else {
            *(float4*)&g_Kf[node * HID + (oq - 16) * 4] = r;
            __half2* kh = (__half2*)&g_Kh[node * HID + (oq - 16) * 4];
            kh[0] = __floats2half2_rn(r.x, r.y);
            kh[1] = __floats2half2_rn(r.z, r.w);
        }
    } else {
        *(float4*)&g_V[node * NC + (oq - 32) * 4] = acc;
        __half2* vh = (__half2*)&g_Vh[node * NC + (oq - 32) * 4];
        vh[0] = __floats2half2_rn(acc.x, acc.y);
        vh[1] = __floats2half2_rn(acc.z, acc.w);
    }
}

// ---------------- teleport reduction ---------------------------------------
__global__ void k_tele() {
    __shared__ __align__(16) float sK[8 * HID];
    __shared__ __align__(16) float sV[8 * NC];
    int tid = threadIdx.x;  // 256
    float accM[8];
#pragma unroll
    for (int j = 0; j < 8; j++) accM[j] = 0.f;
    float accK = 0.f;
    for (int nb = blockIdx.x * 8; nb < NN; nb += gridDim.x * 8) {
        __syncthreads();
        for (int i = tid; i < 8 * HID; i += 256) {
            int n = i >> 6, f = i & 63;
            int node = nb + n;
            sK[i] = (node < NN) ? g_Kf[node * HID + f] : 0.f;
        }
        for (int i = tid; i < 8 * NC; i += 256) {
            int n = i >> 5, c = i & 31;
            int node = nb + n;
            sV[i] = (node < NN) ? g_V[node * NC + c] : 0.f;
        }
        __syncthreads();
#pragma unroll
        for (int j = 0; j < 8; j++) {
            int cell = j * 256 + tid;
            int ii = cell >> 5, cc = cell & 31;
            float a = 0.f;
#pragma unroll
            for (int n = 0; n < 8; n++) a += sK[n * HID + ii] * sV[n * NC + cc];
            accM[j] += a;
        }
        if (tid < HID) {
            float a = 0.f;
#pragma unroll
            for (int n = 0; n < 8; n++) a += sK[n * HID + tid];
            accK += a;
        }
    }
#pragma unroll
    for (int j = 0; j < 8; j++) atomicAdd(&g_tM[j * 256 + tid], accM[j]);
    if (tid < HID) atomicAdd(&g_tK[tid], accK);
}

// hidden init: hopwise[0]*V + teleport * (Q@tM/n) / (Q.tK/n + CST)
__global__ void k_init(const float* __restrict__ hopwise,
                       const float* __restrict__ teleport,
                       float* __restrict__ out) {
    __shared__ __align__(16) float sM[HID * NC];
    __shared__ float sKn[HID];
    int tid = threadIdx.x;
    const float inv_n = 1.0f / (float)NN;
    for (int i = tid; i < HID * NC; i += 256) sM[i] = g_tM[i] * inv_n;
    if (tid < HID) sKn[tid] = g_tK[tid] * inv_n;
    __syncthreads();
    int w = tid >> 5, lane = tid & 31;
    int j = blockIdx.x * 8 + w;
    if (j >= NN) return;
    float q0 = g_Q[j * HID + lane];
    float q1 = g_Q[j * HID + 32 + lane];
    float th = 0.f;
#pragma unroll
    for (int i = 0; i < 32; i++) th += __shfl_sync(FULL, q0, i) * sM[i * NC + lane];
#pragma unroll
    for (int i = 0; i < 32; i++) th += __shfl_sync(FULL, q1, i) * sM[(i + 32) * NC + lane];
    float p = q0 * sKn[lane] + q1 * sKn[32 + lane];
#pragma unroll
    for (int o = 16; o > 0; o >>= 1) p += __shfl_xor_sync(FULL, p, o);
    float tc = p + CSTF;
    out[j * NC + lane] = hopwise[0] * g_V[j * NC + lane] + teleport[0] * th / tc;
}

// ---------------- Kf propagation (fp16 rows) + coef ------------------------
__global__ void k_propK(int in_sel, int out_sel, const float* __restrict__ hopwise, int hop) {
    const __half* Kin = in_sel == 0 ? g_Kh : (in_sel == 1 ? g_Kha : g_Khb);
    __half* Kout = out_sel == 1 ? g_Kha : g_Khb;
    int w = threadIdx.x >> 5, lane = threadIdx.x & 31;
    int j = blockIdx.x * 8 + w;
    if (j >= NN) return;
    int r0 = g_cptr[j], r1 = g_cptr[j + 1];
    float2 acc = make_float2(0.f, 0.f);
    int off = 2 * lane;
    for (int base = r0; base < r1; base += 32) {
        int idx = base + lane;
        int s = 0; float ww = 0.f;
        if (idx < r1) {
            float2 sw = g_swp[idx];
            s = __float_as_int(sw.x); ww = sw.y;
        }
        int mm = min(32, r1 - base);
        int mmr = (mm + 3) & ~3;
        for (int i = 0; i < mmr; i += 4) {
            int s0 = __shfl_sync(FULL, s, i);
            int s1 = __shfl_sync(FULL, s, i + 1);
            int s2 = __shfl_sync(FULL, s, i + 2);
            int s3 = __shfl_sync(FULL, s, i + 3);
            float w0 = __shfl_sync(FULL, ww, i);
            float w1 = __shfl_sync(FULL, ww, i + 1);
            float w2 = __shfl_sync(FULL, ww, i + 2);
            float w3 = __shfl_sync(FULL, ww, i + 3);
            float2 k0 = __half22float2(*(const __half2*)&Kin[s0 * HID + off]);
            float2 k1 = __half22float2(*(const __half2*)&Kin[s1 * HID + off]);
            float2 k2 = __half22float2(*(const __half2*)&Kin[s2 * HID + off]);
            float2 k3 = __half22float2(*(const __half2*)&Kin[s3 * HID + off]);
            acc.x += w0 * k0.x; acc.y += w0 * k0.y;
            acc.x += w1 * k1.x; acc.y += w1 * k1.y;
            acc.x += w2 * k2.x; acc.y += w2 * k2.y;
            acc.x += w3 * k3.x; acc.y += w3 * k3.y;
        }
    }
    *(__half2*)&Kout[j * HID + off] = __floats2half2_rn(acc.x, acc.y);
    float2 q = *(const float2*)&g_Q[j * HID + off];
    float p = q.x * acc.x + q.y * acc.y;
#pragma unroll
    for (int o = 16; o > 0; o >>= 1) p += __shfl_xor_sync(FULL, p, o);
    if (lane == 0) g_coef[(hop - 1) * NN + j] = hopwise[hop] / (p + CSTF);
}

// ---------------- shared epilogue: Q-contract + out accumulate --------------
__device__ __forceinline__ void epilogue(float f[8], int j, int lane, int qoff,
                                         const float* coefh, float* out) {
    float qv = g_Q[j * HID + qoff + (lane >> 2)];
#pragma unroll
    for (int m = 0; m < 8; m++) f[m] *= qv;
#pragma unroll
    for (int mask = 4; mask <= 16; mask <<= 1) {
#pragma unroll
        for (int m = 0; m < 8; m++) f[m] += __shfl_xor_sync(FULL, f[m], mask);
    }
    if (lane < 4) {
        float cf = coefh[j];
        float4* o = (float4*)&out[j * NC + lane * 8];
        float4 o0 = o[0], o1 = o[1];
        o0.x += cf * f[0]; o0.y += cf * f[1]; o0.z += cf * f[2]; o0.w += cf * f[3];
        o1.x += cf * f[4]; o1.y += cf * f[5]; o1.z += cf * f[6]; o1.w += cf * f[7];
        o[0] = o0; o[1] = o1;
    }
}

// quantize row (32 lanes x 8 vals) to SIGNED int8 with per-row scale; store
// and publish the row scale into the writer instance's slot array
__device__ __forceinline__ void quant_store(const float f[8], int j, int lane,
                                            uint2* __restrict__ Xout,
                                            float* __restrict__ sOut, int inst) {
    float m = 0.f;
#pragma unroll
    for (int t = 0; t < 8; t++) m = fmaxf(m, fabsf(f[t]));
#pragma unroll
    for (int o = 16; o > 0; o >>= 1) m = fmaxf(m, __shfl_xor_sync(FULL, m, o));
    float inv = (m > 0.f) ? __fdividef(127.f, m) : 0.f;
    int q[8];
#pragma unroll
    for (int t = 0; t < 8; t++) q[t] = __float2int_rn(f[t] * inv);  // [-127,127]
    unsigned lo = (q[0] & 255) | ((q[1] & 255) << 8) | ((q[2] & 255) << 16) | ((unsigned)(q[3] & 255) << 24);
    unsigned hi = (q[4] & 255) | ((q[5] & 255) << 8) | ((q[6] & 255) << 16) | ((unsigned)(q[7] & 255) << 24);
    Xout[j * 32 + lane] = make_uint2(lo, hi);
    if (lane == 0) {
        float s = m * (1.f / 127.f);
        sOut[j] = s;
        atomicMax(&g_slotU[inst * 256 + (j & 255)], __float_as_uint(s));
    }
}

__device__ __forceinline__ void acc8h(float f[8], uint4 xv, float wv) {
    float2 p0 = __half22float2(*(__half2*)&xv.x);
    float2 p1 = __half22float2(*(__half2*)&xv.y);
    float2 p2 = __half22float2(*(__half2*)&xv.z);
    float2 p3 = __half22float2(*(__half2*)&xv.w);
    f[0] += wv * p0.x; f[1] += wv * p0.y;
    f[2] += wv * p1.x; f[3] += wv * p1.y;
    f[4] += wv * p2.x; f[5] += wv * p2.y;
    f[6] += wv * p3.x; f[7] += wv * p3.y;
}

// ---------------- global-rescale kernel: per-row int8 -> global-scale int8 --
__global__ void k_quant(int inst, int swap) {
    uint2* X = swap ? g_X8b : g_X8a;
    const float* sArr = swap ? g_sB : g_sA;
    __shared__ float red[256];
    int tid = threadIdx.x;
    red[tid] = __uint_as_float(g_slotU[inst * 256 + tid]);
    __syncthreads();
    for (int o = 128; o > 0; o >>= 1) {
        if (tid < o) red[tid] = fmaxf(red[tid], red[tid + o]);
        __syncthreads();
    }
    float GS = red[0];
    if (blockIdx.x == 0 && tid == 0) g_GS[inst] = GS;
    int w = tid >> 5, lane = tid & 31;
    int j = blockIdx.x * 8 + w;
    if (j >= NN) return;
    float ratio = (GS > 0.f) ? __fdividef(sArr[j], GS) : 0.f;
    uint2 x = X[j * 32 + lane];
    int q[8];
    q[0] = (int)(signed char)(x.x);
    q[1] = (int)(signed char)(x.x >> 8);
    q[2] = (int)(signed char)(x.x >> 16);
    q[3] = ((int)x.x) >> 24;
    q[4] = (int)(signed char)(x.y);
    q[5] = (int)(signed char)(x.y >> 8);
    q[6] = (int)(signed char)(x.y >> 16);
    q[7] = ((int)x.y) >> 24;
    int p[8];
#pragma unroll
    for (int t = 0; t < 8; t++) p[t] = __float2int_rn((float)q[t] * ratio);
    unsigned lo = (p[0] & 255) | ((p[1] & 255) << 8) | ((p[2] & 255) << 16) | ((unsigned)(p[3] & 255) << 24);
    unsigned hi = (p[4] & 255) | ((p[5] & 255) << 8) | ((p[6] & 255) << 16) | ((unsigned)(p[7] & 255) << 24);
    X[j * 32 + lane] = make_uint2(lo, hi);
}

// ---------------- hop 1: rank-1 fused gather (Kf ⊗ V) -> per-row int8 ------
__global__ void k_prop1(int qoff, int inst, float* __restrict__ out) {
    int w = threadIdx.x >> 5, lane = threadIdx.x & 31;
    int j = blockIdx.x * 8 + w;
    if (j >= NN) return;
    int r0 = g_cptr[j], r1 = g_cptr[j + 1];
    int kk = qoff + (lane >> 2);
    int c0 = (lane & 3) * 8;
    float f[8];
#pragma unroll
    for (int m = 0; m < 8; m++) f[m] = 0.f;
    for (int base = r0; base < r1; base += 32) {
        int idx = base + lane;
        int s = 0; float ww = 0.f;
        if (idx < r1) {
            float2 sw = g_swp[idx];
            s = __float_as_int(sw.x); ww = sw.y;
        }
        int mm = min(32, r1 - base);
        int mmr = (mm + 3) & ~3;
        for (int i = 0; i < mmr; i += 4) {
            int s0 = __shfl_sync(FULL, s, i);
            int s1 = __shfl_sync(FULL, s, i + 1);
            int s2 = __shfl_sync(FULL, s, i + 2);
            int s3 = __shfl_sync(FULL, s, i + 3);
            float w0 = __shfl_sync(FULL, ww, i);
            float w1 = __shfl_sync(FULL, ww, i + 1);
            float w2 = __shfl_sync(FULL, ww, i + 2);
            float w3 = __shfl_sync(FULL, ww, i + 3);
            uint4 v0 = *(const uint4*)&g_Vh[s0 * NC + c0];
            uint4 v1 = *(const uint4*)&g_Vh[s1 * NC + c0];
            uint4 v2 = *(const uint4*)&g_Vh[s2 * NC + c0];
            uint4 v3 = *(const uint4*)&g_Vh[s3 * NC + c0];
            float k0 = w0 * __half2float(g_Kh[s0 * HID + kk]);
            float k1 = w1 * __half2float(g_Kh[s1 * HID + kk]);
            float k2 = w2 * __half2float(g_Kh[s2 * HID + kk]);
            float k3 = w3 * __half2float(g_Kh[s3 * HID + kk]);
            acc8h(f, v0, k0);
            acc8h(f, v1, k1);
            acc8h(f, v2, k2);
            acc8h(f, v3, k3);
        }
    }
    quant_store(f, j, lane, g_X8b, g_sB, inst);
    epilogue(f, j, lane, qoff, g_coef, out);
}

// ---------------- hops 2..4: global-scale int8 gather with DP4A -------------
__global__ void k_propM(int swap, int writeX, int hop, int qoff,
                        int inst_in, int inst_out, float* __restrict__ out) {
    const uint2* Xin = swap ? g_X8b : g_X8a;
    uint2* Xout = swap ? g_X8a : g_X8b;
    float* sOut = swap ? g_sA : g_sB;
    const float* coefh = g_coef + (hop - 1) * NN;
    int w = threadIdx.x >> 5, lane = threadIdx.x & 31;
    int j = blockIdx.x * 8 + w;
    if (j >= NN) return;
    int r0 = g_cptr[j], r1 = g_cptr[j + 1];
    float GSin = g_GS[inst_in];
    float rwj = __uint_as_float(g_rwU[j]);
    int acc[8];
#pragma unroll
    for (int m = 0; m < 8; m++) acc[m] = 0;
    for (int base = r0; base < r1; base += 32) {
        int idx = base + lane;
        unsigned pv = 0;
        if (idx < r1) pv = g_sw8[idx];
        int mm = min(32, r1 - base);
        int mmr = (mm + 3) & ~3;
        for (int i = 0; i < mmr; i += 4) {
            unsigned v0 = __shfl_sync(FULL, pv, i);
            unsigned v1 = __shfl_sync(FULL, pv, i + 1);
            unsigned v2 = __shfl_sync(FULL, pv, i + 2);
            unsigned v3 = __shfl_sync(FULL, pv, i + 3);
            int s0 = v0 & 0xFFFF;
            int s1 = v1 & 0xFFFF;
            int s2 = v2 & 0xFFFF;
            int s3 = v3 & 0xFFFF;
            // pack the 4 w8 bytes (byte 2 of each word)
            unsigned t0 = __byte_perm(v0, v1, 0x0062);
            unsigned t1 = __byte_perm(v2, v3, 0x6200);
            int wp = (int)__byte_perm(t0, t1, 0x7610);
            uint2 x0 = Xin[s0 * 32 + lane];
            uint2 x1 = Xin[s1 * 32 + lane];
            uint2 x2 = Xin[s2 * 32 + lane];
            uint2 x3 = Xin[s3 * 32 + lane];
#pragma unroll
            for (int m = 0; m < 4; m++) {
                unsigned slo = 0x40u + (unsigned)m * 0x11u;          // bytes m of a,b -> 0,1
                unsigned shi = 0x4000u + (unsigned)m * 0x1100u;      // bytes m of a,b -> 2,3
                unsigned qa = __byte_perm(x0.x, x1.x, slo);
                unsigned qb = __byte_perm(x2.x, x3.x, shi);
                int qw = (int)__byte_perm(qa, qb, 0x7610);
                acc[m] = __dp4a(qw, wp, acc[m]);
                unsigned qa2 = __byte_perm(x0.y, x1.y, slo);
                unsigned qb2 = __byte_perm(x2.y, x3.y, shi);
                int qw2 = (int)__byte_perm(qa2, qb2, 0x7610);
                acc[m + 4] = __dp4a(qw2, wp, acc[m + 4]);
            }
        }
    }
    // dequant: x = q'*GSin, w = w8*rwj/127  =>  f = acc * GSin*rwj/127
    float dq = GSin * rwj * (1.f / 127.f);
    float f[8];
#pragma unroll
    for (int m = 0; m < 8; m++) f[m] = (float)acc[m] * dq;
    if (writeX) quant_store(f, j, lane, Xout, sOut, inst_out);
    epilogue(f, j, lane, qoff, coefh, out);
}

// ---------------- launch ----------------------------------------------------
extern "C" void kernel_launch(void* const* d_in, const int* in_sizes, int n_in,
                              void* d_out, int out_size) {
    const float* nf       = (const float*)d_in[0];
    const float* W_in     = (const float*)d_in[1];
    const float* b_in     = (const float*)d_in[2];
    const float* WQ       = (const float*)d_in[3];
    const float* bQ       = (const float*)d_in[4];
    const float* WK       = (const float*)d_in[5];
    const float* bK       = (const float*)d_in[6];
    const float* WV       = (const float*)d_in[7];
    const float* bV       = (const float*)d_in[8];
    const float* hopwise  = (const float*)d_in[9];
    const float* teleport = (const float*)d_in[10];
    const int*   ei       = (const int*)d_in[11];
    const int* row = ei;
    const int* col = ei + EE;
    float* out = (float*)d_out;

    k_zero<<<(NN + 255) / 256, 256>>>();
    k_hist<<<EE / 256, 256>>>(col);
    k_dinv<<<(NN + 255) / 256, 256>>>();
    k_wmax<<<EE / 256, 256>>>(row, col);
    k_blksum<<<NBLK, 256>>>();
    k_scanblk<<<1, 256>>>();
    k_cptr<<<NBLK, 256>>>();
    k_scatter<<<EE / 256, 256>>>(row, col);
    k_gemmA<<<NN / 16, dim3(16, 16)>>>(nf, W_in, b_in);
    k_gemmB<<<NN / 8, dim3(40, 8)>>>(WQ, bQ, WK, bK, WV, bV);
    k_tele<<<200, 256>>>();
    k_init<<<NN / 8, 256>>>(hopwise, teleport, out);
    // Kf hops (fp16 rows): Kh -> Ka -> Kb -> Ka -> Kb; coef per hop
    k_propK<<<NN / 8, 256>>>(0, 1, hopwise, 1);
    k_propK<<<NN / 8, 256>>>(1, 2, hopwise, 2);
    k_propK<<<NN / 8, 256>>>(2, 1, hopwise, 3);
    k_propK<<<NN / 8, 256>>>(1, 2, hopwise, 4);
    // M propagation per 8-wide k-group; hop1 fused rank-1; hops 2-4 DP4A int8
    for (int g = 0; g < NG; g++) {
        int i0 = g * 3, i1 = g * 3 + 1, i2 = g * 3 + 2;
        k_prop1<<<NN / 8, 256>>>(g * GK, i0, out);                    // -> X8b (per-row)
        k_quant<<<NN / 8, 256>>>(i0, 1);                              // X8b -> global scale
        k_propM<<<NN / 8, 256>>>(1, 1, 2, g * GK, i0, i1, out);       // X8b -> X8a (per-row)
        k_quant<<<NN / 8, 256>>>(i1, 0);                              // X8a -> global scale
        k_propM<<<NN / 8, 256>>>(0, 1, 3, g * GK, i1, i2, out);       // X8a -> X8b (per-row)
        k_quant<<<NN / 8, 256>>>(i2, 1);                              // X8b -> global scale
        k_propM<<<NN / 8, 256>>>(1, 0, 4, g * GK, i2, 0, out);        // X8b, no write
    }
}

// round 13
// speedup vs baseline: 1.1992x; 1.0482x over previous
#include <cuda_runtime.h>
#include <cuda_fp16.h>
#include <math.h>

#define NN 50000
#define EE 1600000
#define HID 64
#define NC 32
#define NFEAT 128
#define NG 4           // k-groups (64/16)
#define GK 16          // k-cols per group
#define GWH 512        // halves per X row = GK*NC
#define CSTF 1e-5f
#define FULL 0xffffffffu
#define NBLK ((NN + 255) / 256)

// ---------------- scratch (device globals; no allocation allowed) ----------
__device__ int    g_deg[NN];
__device__ float  g_dinv[NN];
__device__ int    g_cptr[NN + 1];
__device__ int    g_cnt[NN];
__device__ float2 g_swp[EE];      // packed (src-as-float-bits, wgt)
__device__ int    g_bsum[NBLK];
__device__ int    g_boff[NBLK];
__device__ float  g_x[NN * HID];
__device__ float  g_Q[NN * HID];
__device__ float  g_Kf[NN * HID];
__device__ float  g_V[NN * NC];
__device__ __half g_Kh[NN * HID];
__device__ __half g_Vh[NN * NC];
__device__ __half g_Kha[NN * HID];
__device__ __half g_Khb[NN * HID];
__device__ float  g_coef[4 * NN];
__device__ float  g_tM[HID * NC];
__device__ float  g_tK[HID];
__device__ __half g_Xa[NN * GWH];   // 51.2 MB
__device__ __half g_Xb[NN * GWH];   // 51.2 MB

// ---------------- setup kernels --------------------------------------------
__global__ void k_zero() {
    int i = blockIdx.x * blockDim.x + threadIdx.x;
    if (i < NN) { g_deg[i] = 0; g_cnt[i] = 0; }
    if (i < HID * NC) g_tM[i] = 0.f;
    if (i < HID) g_tK[i] = 0.f;
}

__global__ void k_hist(const int* __restrict__ col) {
    int e = blockIdx.x * blockDim.x + threadIdx.x;
    if (e < EE) atomicAdd(&g_deg[col[e]], 1);
}

__global__ void k_dinv() {
    int i = blockIdx.x * blockDim.x + threadIdx.x;
    if (i < NN) {
        int d = g_deg[i];
        g_dinv[i] = (d > 0) ? 1.0f / (float)d : 0.0f;
    }
}

__global__ void k_blksum() {
    __shared__ int sm[256];
    int b = blockIdx.x, t = threadIdx.x;
    int i = b * 256 + t;
    sm[t] = (i < NN) ? g_deg[i] : 0;
    __syncthreads();
    for (int o = 128; o > 0; o >>= 1) {
        if (t < o) sm[t] += sm[t + o];
        __syncthreads();
    }
    if (t == 0) g_bsum[b] = sm[0];
}

__global__ void k_scanblk() {
    __shared__ int sm[256];
    int t = threadIdx.x;
    int v = (t < NBLK) ? g_bsum[t] : 0;
    sm[t] = v;
    __syncthreads();
    for (int o = 1; o < 256; o <<= 1) {
        int u = 0;
        if (t >= o) u = sm[t - o];
        __syncthreads();
        sm[t] += u;
        __syncthreads();
    }
    if (t < NBLK) g_boff[t] = sm[t] - v;
}

__global__ void k_cptr() {
    __shared__ int sm[256];
    int b = blockIdx.x, t = threadIdx.x;
    int i = b * 256 + t;
    int v = (i < NN) ? g_deg[i] : 0;
    sm[t] = v;
    __syncthreads();
    for (int o = 1; o < 256; o <<= 1) {
        int u = 0;
        if (t >= o) u = sm[t - o];
        __syncthreads();
        sm[t] += u;
        __syncthreads();
    }
    int incl = sm[t];
    if (i < NN) g_cptr[i] = g_boff[b] + incl - v;
    if (i == NN - 1) g_cptr[NN] = g_boff[b] + incl;
}

__global__ void k_scatter(const int* __restrict__ row, const int* __restrict__ col) {
    int e = blockIdx.x * blockDim.x + threadIdx.x;
    if (e < EE) {
        int c = col[e];
        int r = row[e];
        int pos = g_cptr[c] + atomicAdd(&g_cnt[c], 1);
        g_swp[pos] = make_float2(__int_as_float(r), g_dinv[r]);
    }
}

// ---------------- input GEMMs ----------------------------------------------
__global__ void k_gemmA(const float* __restrict__ nf, const float* __restrict__ W,
                        const float* __restrict__ b) {
    __shared__ __align__(16) float Ws[NFEAT * HID];
    __shared__ __align__(16) float xs[16 * NFEAT];
    __shared__ __align__(16) float bs[HID];
    int tid = threadIdx.y * 16 + threadIdx.x;
    for (int i = tid; i < NFEAT * HID; i += 256) Ws[i] = W[i];
    if (tid < HID) bs[tid] = b[tid];
    int nb = blockIdx.x * 16;
    for (int i = tid; i < 16 * NFEAT; i += 256) {
        int n = i >> 7, f = i & 127;
        xs[i] = nf[(nb + n) * NFEAT + f];
    }
    __syncthreads();
    int node = nb + threadIdx.y;
    int oq = threadIdx.x;
    float4 acc = *(const float4*)&bs[oq * 4];
    const float* xr = &xs[threadIdx.y * NFEAT];
#pragma unroll 8
    for (int f = 0; f < NFEAT; f++) {
        float v = xr[f];
        float4 w = *(const float4*)&Ws[f * HID + oq * 4];
        acc.x += v * w.x; acc.y += v * w.y; acc.z += v * w.z; acc.w += v * w.w;
    }
    acc.x = fmaxf(acc.x, 0.f); acc.y = fmaxf(acc.y, 0.f);
    acc.z = fmaxf(acc.z, 0.f); acc.w = fmaxf(acc.w, 0.f);
    *(float4*)&g_x[node * HID + oq * 4] = acc;
}

__global__ void k_gemmB(const float* __restrict__ WQ, const float* __restrict__ bQ,
                        const float* __restrict__ WK, const float* __restrict__ bK,
                        const float* __restrict__ WV, const float* __restrict__ bV) {
    __shared__ __align__(16) float Wc[HID * 160];
    __shared__ __align__(16) float xs[8 * HID];
    __shared__ __align__(16) float bc[160];
    int tid = threadIdx.y * 40 + threadIdx.x;  // 320 threads
    for (int i = tid; i < HID * 160; i += 320) {
        int f = i / 160, o = i % 160;
        float v;
        if (o < 64) v = WQ[f * 64 + o];
        else if (o < 128) v = WK[f * 64 + (o - 64)];
        else v = WV[f * 32 + (o - 128)];
        Wc[i] = v;
    }
    if (tid < 160)
        bc[tid] = (tid < 64) ? bQ[tid] : ((tid < 128) ? bK[tid - 64] : bV[tid - 128]);
    int nb = blockIdx.x * 8;
    for (int i = tid; i < 8 * HID; i += 320) {
        int n = i >> 6, f = i & 63;
        xs[i] = g_x[(nb + n) * HID + f];
    }
    __syncthreads();
    int node = nb + threadIdx.y;
    int oq = threadIdx.x;
    float4 acc = *(const float4*)&bc[oq * 4];
    const float* xr = &xs[threadIdx.y * HID];
#pragma unroll 8
    for (int f = 0; f < HID; f++) {
        float v = xr[f];
        float4 w = *(const float4*)&Wc[f * 160 + oq * 4];
        acc.x += v * w.x; acc.y += v * w.y; acc.z += v * w.z; acc.w += v * w.w;
    }
    if (oq < 32) {
        float4 r;
        r.x = acc.x > 0.f ? 1.f + acc.x : expf(acc.x);
        r.y = acc.y > 0.f ? 1.f + acc.y : expf(acc.y);
        r.z = acc.z > 0.f ? 1.f + acc.z : expf(acc.z);
        r.w = acc.w > 0.f ? 1.f + acc.w : expf(acc.w);
        if (oq < 16) {
            *(float4*)&g_Q[node * HID + oq * 4] = r;
        } else {
            *(float4*)&g_Kf[node * HID + (oq - 16) * 4] = r;
            __half2* kh = (__half2*)&g_Kh[node * HID + (oq - 16) * 4];
            kh[0] = __floats2half2_rn(r.x, r.y);
            kh[1] = __floats2half2_rn(r.z, r.w);
        }
    } else {
        *(float4*)&g_V[node * NC + (oq - 32) * 4] = acc;
        __half2* vh = (__half2*)&g_Vh[node * NC + (oq - 32) * 4];
        vh[0] = __floats2half2_rn(acc.x, acc.y);
        vh[1] = __floats2half2_rn(acc.z, acc.w);
    }
}

// ---------------- teleport reduction ---------------------------------------
__global__ void k_tele() {
    __shared__ __align__(16) float sK[8 * HID];
    __shared__ __align__(16) float sV[8 * NC];
    int tid = threadIdx.x;  // 256
    float accM[8];
#pragma unroll
    for (int j = 0; j < 8; j++) accM[j] = 0.f;
    float accK = 0.f;
    for (int nb = blockIdx.x * 8; nb < NN; nb += gridDim.x * 8) {
        __syncthreads();
        for (int i = tid; i < 8 * HID; i += 256) {
            int n = i >> 6, f = i & 63;
            int node = nb + n;
            sK[i] = (node < NN) ? g_Kf[node * HID + f] : 0.f;
        }
        for (int i = tid; i < 8 * NC; i += 256) {
            int n = i >> 5, c = i & 31;
            int node = nb + n;
            sV[i] = (node < NN) ? g_V[node * NC + c] : 0.f;
        }
        __syncthreads();
#pragma unroll
        for (int j = 0; j < 8; j++) {
            int cell = j * 256 + tid;
            int ii = cell >> 5, cc = cell & 31;
            float a = 0.f;
#pragma unroll
            for (int n = 0; n < 8; n++) a += sK[n * HID + ii] * sV[n * NC + cc];
            accM[j] += a;
        }
        if (tid < HID) {
            float a = 0.f;
#pragma unroll
            for (int n = 0; n < 8; n++) a += sK[n * HID + tid];
            accK += a;
        }
    }
#pragma unroll
    for (int j = 0; j < 8; j++) atomicAdd(&g_tM[j * 256 + tid], accM[j]);
    if (tid < HID) atomicAdd(&g_tK[tid], accK);
}

// hidden init: hopwise[0]*V + teleport * (Q@tM/n) / (Q.tK/n + CST)
__global__ void k_init(const float* __restrict__ hopwise,
                       const float* __restrict__ teleport,
                       float* __restrict__ out) {
    __shared__ __align__(16) float sM[HID * NC];
    __shared__ float sKn[HID];
    int tid = threadIdx.x;
    const float inv_n = 1.0f / (float)NN;
    for (int i = tid; i < HID * NC; i += 256) sM[i] = g_tM[i] * inv_n;
    if (tid < HID) sKn[tid] = g_tK[tid] * inv_n;
    __syncthreads();
    int w = tid >> 5, lane = tid & 31;
    int j = blockIdx.x * 8 + w;
    if (j >= NN) return;
    float q0 = g_Q[j * HID + lane];
    float q1 = g_Q[j * HID + 32 + lane];
    float th = 0.f;
#pragma unroll
    for (int i = 0; i < 32; i++) th += __shfl_sync(FULL, q0, i) * sM[i * NC + lane];
#pragma unroll
    for (int i = 0; i < 32; i++) th += __shfl_sync(FULL, q1, i) * sM[(i + 32) * NC + lane];
    float p = q0 * sKn[lane] + q1 * sKn[32 + lane];
#pragma unroll
    for (int o = 16; o > 0; o >>= 1) p += __shfl_xor_sync(FULL, p, o);
    float tc = p + CSTF;
    out[j * NC + lane] = hopwise[0] * g_V[j * NC + lane] + teleport[0] * th / tc;
}

// ---------------- Kf propagation (fp16 rows) + coef ------------------------
__global__ void k_propK(int in_sel, int out_sel, const float* __restrict__ hopwise, int hop) {
    const __half* Kin = in_sel == 0 ? g_Kh : (in_sel == 1 ? g_Kha : g_Khb);
    __half* Kout = out_sel == 1 ? g_Kha : g_Khb;
    int w = threadIdx.x >> 5, lane = threadIdx.x & 31;
    int j = blockIdx.x * 8 + w;
    if (j >= NN) return;
    int r0 = g_cptr[j], r1 = g_cptr[j + 1];
    float2 acc = make_float2(0.f, 0.f);
    int off = 2 * lane;
    for (int base = r0; base < r1; base += 32) {
        int idx = base + lane;
        int s = 0; float ww = 0.f;
        if (idx < r1) {
            float2 sw = g_swp[idx];
            s = __float_as_int(sw.x); ww = sw.y;
        }
        int mm = min(32, r1 - base);
        int mmr = (mm + 3) & ~3;
        for (int i = 0; i < mmr; i += 4) {
            int s0 = __shfl_sync(FULL, s, i);
            int s1 = __shfl_sync(FULL, s, i + 1);
            int s2 = __shfl_sync(FULL, s, i + 2);
            int s3 = __shfl_sync(FULL, s, i + 3);
            float w0 = __shfl_sync(FULL, ww, i);
            float w1 = __shfl_sync(FULL, ww, i + 1);
            float w2 = __shfl_sync(FULL, ww, i + 2);
            float w3 = __shfl_sync(FULL, ww, i + 3);
            float2 k0 = __half22float2(*(const __half2*)&Kin[s0 * HID + off]);
            float2 k1 = __half22float2(*(const __half2*)&Kin[s1 * HID + off]);
            float2 k2 = __half22float2(*(const __half2*)&Kin[s2 * HID + off]);
            float2 k3 = __half22float2(*(const __half2*)&Kin[s3 * HID + off]);
            acc.x += w0 * k0.x; acc.y += w0 * k0.y;
            acc.x += w1 * k1.x; acc.y += w1 * k1.y;
            acc.x += w2 * k2.x; acc.y += w2 * k2.y;
            acc.x += w3 * k3.x; acc.y += w3 * k3.y;
        }
    }
    *(__half2*)&Kout[j * HID + off] = __floats2half2_rn(acc.x, acc.y);
    float2 q = *(const float2*)&g_Q[j * HID + off];
    float p = q.x * acc.x + q.y * acc.y;
#pragma unroll
    for (int o = 16; o > 0; o >>= 1) p += __shfl_xor_sync(FULL, p, o);
    if (lane == 0) g_coef[(hop - 1) * NN + j] = hopwise[hop] / (p + CSTF);
}

// ---------------- 16-wide epilogue: Q-contract + out accumulate -------------
// lane l holds 16 c-values for k = qoff + (l>>1), c = (l&1)*16 .. +16
__device__ __forceinline__ void epilogue16(float f[16], int j, int lane, int qoff,
                                           const float* coefh, float* out) {
    float qv = g_Q[j * HID + qoff + (lane >> 1)];
#pragma unroll
    for (int m = 0; m < 16; m++) f[m] *= qv;
#pragma unroll
    for (int mask = 2; mask <= 16; mask <<= 1) {
#pragma unroll
        for (int m = 0; m < 16; m++) f[m] += __shfl_xor_sync(FULL, f[m], mask);
    }
    if (lane < 2) {
        float cf = coefh[j];
        float4* o = (float4*)&out[j * NC + lane * 16];
#pragma unroll
        for (int v = 0; v < 4; v++) {
            float4 ov = o[v];
            ov.x += cf * f[v * 4 + 0]; ov.y += cf * f[v * 4 + 1];
            ov.z += cf * f[v * 4 + 2]; ov.w += cf * f[v * 4 + 3];
            o[v] = ov;
        }
    }
}

__device__ __forceinline__ void acc16h(float f[16], uint4 a, uint4 b, float wv) {
    const unsigned* pa = (const unsigned*)&a;
    const unsigned* pb = (const unsigned*)&b;
#pragma unroll
    for (int t = 0; t < 4; t++) {
        float2 p = __half22float2(*(__half2*)&pa[t]);
        f[2 * t]     += wv * p.x;
        f[2 * t + 1] += wv * p.y;
    }
#pragma unroll
    for (int t = 0; t < 4; t++) {
        float2 p = __half22float2(*(__half2*)&pb[t]);
        f[8 + 2 * t]     += wv * p.x;
        f[8 + 2 * t + 1] += wv * p.y;
    }
}

__device__ __forceinline__ void store16(const float f[16], __half* dst) {
    uint4 s0, s1;
    ((__half2*)&s0)[0] = __floats2half2_rn(f[0], f[1]);
    ((__half2*)&s0)[1] = __floats2half2_rn(f[2], f[3]);
    ((__half2*)&s0)[2] = __floats2half2_rn(f[4], f[5]);
    ((__half2*)&s0)[3] = __floats2half2_rn(f[6], f[7]);
    ((__half2*)&s1)[0] = __floats2half2_rn(f[8], f[9]);
    ((__half2*)&s1)[1] = __floats2half2_rn(f[10], f[11]);
    ((__half2*)&s1)[2] = __floats2half2_rn(f[12], f[13]);
    ((__half2*)&s1)[3] = __floats2half2_rn(f[14], f[15]);
    *(uint4*)dst = s0;
    *(uint4*)(dst + 8) = s1;
}

// ---------------- hop 1: rank-1 fused gather (Kf ⊗ V), writes X1 -> Xb ------
__global__ void k_prop1(int qoff, float* __restrict__ out) {
    int w = threadIdx.x >> 5, lane = threadIdx.x & 31;
    int j = blockIdx.x * 8 + w;
    if (j >= NN) return;
    int r0 = g_cptr[j], r1 = g_cptr[j + 1];
    int kk = qoff + (lane >> 1);
    int c0 = (lane & 1) * 16;
    float f[16];
#pragma unroll
    for (int m = 0; m < 16; m++) f[m] = 0.f;
    for (int base = r0; base < r1; base += 32) {
        int idx = base + lane;
        int s = 0; float ww = 0.f;
        if (idx < r1) {
            float2 sw = g_swp[idx];
            s = __float_as_int(sw.x); ww = sw.y;
        }
        int mm = min(32, r1 - base);
        int mmr = (mm + 3) & ~3;
        for (int i = 0; i < mmr; i += 4) {
            int s0 = __shfl_sync(FULL, s, i);
            int s1 = __shfl_sync(FULL, s, i + 1);
            int s2 = __shfl_sync(FULL, s, i + 2);
            int s3 = __shfl_sync(FULL, s, i + 3);
            float w0 = __shfl_sync(FULL, ww, i);
            float w1 = __shfl_sync(FULL, ww, i + 1);
            float w2 = __shfl_sync(FULL, ww, i + 2);
            float w3 = __shfl_sync(FULL, ww, i + 3);
            const uint4* v0p = (const uint4*)&g_Vh[s0 * NC + c0];
            const uint4* v1p = (const uint4*)&g_Vh[s1 * NC + c0];
            const uint4* v2p = (const uint4*)&g_Vh[s2 * NC + c0];
            const uint4* v3p = (const uint4*)&g_Vh[s3 * NC + c0];
            uint4 a0 = v0p[0], b0 = v0p[1];
            uint4 a1 = v1p[0], b1 = v1p[1];
            uint4 a2 = v2p[0], b2 = v2p[1];
            uint4 a3 = v3p[0], b3 = v3p[1];
            float k0 = w0 * __half2float(g_Kh[s0 * HID + kk]);
            float k1 = w1 * __half2float(g_Kh[s1 * HID + kk]);
            float k2 = w2 * __half2float(g_Kh[s2 * HID + kk]);
            float k3 = w3 * __half2float(g_Kh[s3 * HID + kk]);
            acc16h(f, a0, b0, k0);
            acc16h(f, a1, b1, k1);
            acc16h(f, a2, b2, k2);
            acc16h(f, a3, b3, k3);
        }
    }
    store16(f, &g_Xb[j * GWH + lane * 16]);
    epilogue16(f, j, lane, qoff, g_coef, out);
}

// ---------------- hops 2..4: fp16 X gather, 16-wide ------------------------
__global__ void k_propM(int swap, int writeX, int hop, int qoff, float* __restrict__ out) {
    const __half* Xin = swap ? g_Xb : g_Xa;
    __half* Xout = swap ? g_Xa : g_Xb;
    const float* coefh = g_coef + (hop - 1) * NN;
    int w = threadIdx.x >> 5, lane = threadIdx.x & 31;
    int j = blockIdx.x * 8 + w;
    if (j >= NN) return;
    int r0 = g_cptr[j], r1 = g_cptr[j + 1];
    int off = lane * 16;
    float f[16];
#pragma unroll
    for (int m = 0; m < 16; m++) f[m] = 0.f;
    for (int base = r0; base < r1; base += 32) {
        int idx = base + lane;
        int s = 0; float ww = 0.f;
        if (idx < r1) {
            float2 sw = g_swp[idx];
            s = __float_as_int(sw.x); ww = sw.y;
        }
        int mm = min(32, r1 - base);
        int mmr = (mm + 3) & ~3;
        for (int i = 0; i < mmr; i += 4) {
            int s0 = __shfl_sync(FULL, s, i);
            int s1 = __shfl_sync(FULL, s, i + 1);
            int s2 = __shfl_sync(FULL, s, i + 2);
            int s3 = __shfl_sync(FULL, s, i + 3);
            float w0 = __shfl_sync(FULL, ww, i);
            float w1 = __shfl_sync(FULL, ww, i + 1);
            float w2 = __shfl_sync(FULL, ww, i + 2);
            float w3 = __shfl_sync(FULL, ww, i + 3);
            const uint4* x0p = (const uint4*)&Xin[s0 * GWH + off];
            const uint4* x1p = (const uint4*)&Xin[s1 * GWH + off];
            const uint4* x2p = (const uint4*)&Xin[s2 * GWH + off];
            const uint4* x3p = (const uint4*)&Xin[s3 * GWH + off];
            uint4 a0 = x0p[0], b0 = x0p[1];
            uint4 a1 = x1p[0], b1 = x1p[1];
            uint4 a2 = x2p[0], b2 = x2p[1];
            uint4 a3 = x3p[0], b3 = x3p[1];
            acc16h(f, a0, b0, w0);
            acc16h(f, a1, b1, w1);
            acc16h(f, a2, b2, w2);
            acc16h(f, a3, b3, w3);
        }
    }
    if (writeX) store16(f, &Xout[j * GWH + off]);
    epilogue16(f, j, lane, qoff, coefh, out);
}

// ---------------- launch ----------------------------------------------------
extern "C" void kernel_launch(void* const* d_in, const int* in_sizes, int n_in,
                              void* d_out, int out_size) {
    const float* nf       = (const float*)d_in[0];
    const float* W_in     = (const float*)d_in[1];
    const float* b_in     = (const float*)d_in[2];
    const float* WQ       = (const float*)d_in[3];
    const float* bQ       = (const float*)d_in[4];
    const float* WK       = (const float*)d_in[5];
    const float* bK       = (const float*)d_in[6];
    const float* WV       = (const float*)d_in[7];
    const float* bV       = (const float*)d_in[8];
    const float* hopwise  = (const float*)d_in[9];
    const float* teleport = (const float*)d_in[10];
    const int*   ei       = (const int*)d_in[11];
    const int* row = ei;
    const int* col = ei + EE;
    float* out = (float*)d_out;

    k_zero<<<(NN + 255) / 256, 256>>>();
    k_hist<<<EE / 256, 256>>>(col);
    k_dinv<<<(NN + 255) / 256, 256>>>();
    k_blksum<<<NBLK, 256>>>();
    k_scanblk<<<1, 256>>>();
    k_cptr<<<NBLK, 256>>>();
    k_scatter<<<EE / 256, 256>>>(row, col);
    k_gemmA<<<NN / 16, dim3(16, 16)>>>(nf, W_in, b_in);
    k_gemmB<<<NN / 8, dim3(40, 8)>>>(WQ, bQ, WK, bK, WV, bV);
    k_tele<<<200, 256>>>();
    k_init<<<NN / 8, 256>>>(hopwise, teleport, out);
    // Kf hops (fp16 rows): Kh -> Ka -> Kb -> Ka -> Kb; coef per hop
    k_propK<<<NN / 8, 256>>>(0, 1, hopwise, 1);
    k_propK<<<NN / 8, 256>>>(1, 2, hopwise, 2);
    k_propK<<<NN / 8, 256>>>(2, 1, hopwise, 3);
    k_propK<<<NN / 8, 256>>>(1, 2, hopwise, 4);
    // M propagation per 16-wide k-group; hop1 fused rank-1, hops 2-4 fp16 X
    for (int g = 0; g < NG; g++) {
        k_prop1<<<NN / 8, 256>>>(g * GK, out);          // -> Xb (hop 1)
        k_propM<<<NN / 8, 256>>>(1, 1, 2, g * GK, out); // Xb -> Xa
        k_propM<<<NN / 8, 256>>>(0, 1, 3, g * GK, out); // Xa -> Xb
        k_propM<<<NN / 8, 256>>>(1, 0, 4, g * GK, out); // Xb (no write)
    }
}